// round 13
// baseline (speedup 1.0000x reference)
#include <cuda_runtime.h>
#include <cuda_bf16.h>
#include <cstdint>
#include <math.h>

// Problem constants
#define Bq   2
#define Tq   2048
#define Cq   1024
#define Hq   16
#define HDq  64
#define Mq   2048

// Scratch (allocation-free rule: __device__ globals)
__device__ float         g_k[Bq * Tq * Cq];    // relu(x@w1^T+b1), tf32-rounded
__device__ float         g_v[Bq * Tq * Cq];    // x@value^T+vb, tf32-rounded
__device__ __nv_bfloat16 g_ahi[Bq * Tq * Cq];  // activation hi plane (perm layout)
__device__ __nv_bfloat16 g_alo[Bq * Tq * Cq];  // activation lo plane (perm layout)
__device__ __nv_bfloat16 g_whi[Cq * Cq];       // weight hi plane (perm layout)
__device__ __nv_bfloat16 g_wlo[Cq * Cq];       // weight lo plane (perm layout)
__device__ float         g_w2r[Hq * HDq * Mq]; // w2 tf32-rounded

// ---------------------------------------------------------------------------
// helpers
// ---------------------------------------------------------------------------
__device__ __forceinline__ unsigned f2tf32(float x) {
    unsigned u;
    asm("cvt.rna.tf32.f32 %0, %1;" : "=r"(u) : "f"(x));
    return u;
}

__device__ __forceinline__ void mma_tf32(
    float& d0, float& d1, float& d2, float& d3,
    unsigned a0, unsigned a1, unsigned a2, unsigned a3,
    unsigned b0, unsigned b1)
{
    asm volatile(
        "mma.sync.aligned.m16n8k8.row.col.f32.tf32.tf32.f32 "
        "{%0,%1,%2,%3}, {%4,%5,%6,%7}, {%8,%9}, {%0,%1,%2,%3};"
        : "+f"(d0), "+f"(d1), "+f"(d2), "+f"(d3)
        : "r"(a0), "r"(a1), "r"(a2), "r"(a3), "r"(b0), "r"(b1));
}

__device__ __forceinline__ void mma_bf16(
    float& d0, float& d1, float& d2, float& d3,
    unsigned a0, unsigned a1, unsigned a2, unsigned a3,
    unsigned b0, unsigned b1)
{
    asm volatile(
        "mma.sync.aligned.m16n8k16.row.col.f32.bf16.bf16.f32 "
        "{%0,%1,%2,%3}, {%4,%5,%6,%7}, {%8,%9}, {%0,%1,%2,%3};"
        : "+f"(d0), "+f"(d1), "+f"(d2), "+f"(d3)
        : "r"(a0), "r"(a1), "r"(a2), "r"(a3), "r"(b0), "r"(b1));
}

__device__ __forceinline__ void cp_async16(void* s, const void* g) {
    unsigned sa = (unsigned)__cvta_generic_to_shared(s);
    asm volatile("cp.async.cg.shared.global [%0], [%1], 16;" :: "r"(sa), "l"(g));
}

__device__ __forceinline__ void bf16_split(float v, __nv_bfloat16& h, __nv_bfloat16& l) {
    h = __float2bfloat16_rn(v);
    l = __float2bfloat16_rn(v - __bfloat162float(h));
}

// Word-order permutation within each 8-word (16 bf16) group:
// orig word p -> pos 2p (p<4) / 2p-7 (p>=4). Makes fragment word pairs
// (tg, tg+4) adjacent -> LDS.64 fragment loads.
__device__ __forceinline__ size_t perm_word(size_t w) {
    return (w & ~(size_t)7) | (((w & 3) << 1) | ((w >> 2) & 1));
}

// ---------------------------------------------------------------------------
// Prep kernels
// ---------------------------------------------------------------------------
// Split fp32 -> bf16 hi/lo planes, writing the PERMUTED word layout.
// Thread i covers elements 4i..4i+3 = words 2i, 2i+1 (same 8-word group).
__global__ __launch_bounds__(256) void split_bf16_kernel(
    const float4* __restrict__ in, __nv_bfloat162* __restrict__ hi,
    __nv_bfloat162* __restrict__ lo, int n4)
{
    int i = blockIdx.x * 256 + threadIdx.x;
    if (i < n4) {
        float4 v = in[i];
        __nv_bfloat16 hx, lx, hy, ly, hz, lz, hw, lw;
        bf16_split(v.x, hx, lx);
        bf16_split(v.y, hy, ly);
        bf16_split(v.z, hz, lz);
        bf16_split(v.w, hw, lw);
        __nv_bfloat162 h0; h0.x = hx; h0.y = hy;
        __nv_bfloat162 h1; h1.x = hz; h1.y = hw;
        __nv_bfloat162 l0; l0.x = lx; l0.y = ly;
        __nv_bfloat162 l1; l1.x = lz; l1.y = lw;
        size_t w0 = perm_word((size_t)2 * i);
        size_t w1 = perm_word((size_t)2 * i + 1);
        hi[w0] = h0; hi[w1] = h1;
        lo[w0] = l0; lo[w1] = l1;
    }
}

__global__ __launch_bounds__(256) void round_kernel(
    const float4* __restrict__ in, float4* __restrict__ out, int n4)
{
    int i = blockIdx.x * 256 + threadIdx.x;
    if (i < n4) {
        float4 v = in[i];
        float4 o;
        o.x = __uint_as_float(f2tf32(v.x));
        o.y = __uint_as_float(f2tf32(v.y));
        o.z = __uint_as_float(f2tf32(v.z));
        o.w = __uint_as_float(f2tf32(v.w));
        out[i] = o;
    }
}

// ---------------------------------------------------------------------------
// Dense GEMM via 3x bf16 hi/lo mma (hh+hl+lh), cp.async 2-stage, 2 CTAs/SM,
// permuted-plane layout -> all fragment loads are conflict-free LDS.64:
//   C[M,N] = act(A[M,K] @ W[N,K]^T + bias[N])
// Block 128x128, K-tile 32 elts, smem row stride 24 words (bank-pair
// (12g+tg) mod 16 distinct per phase).
// ---------------------------------------------------------------------------
#define GST   24
#define GPLW  (128 * GST)   // words per plane-stage (3072)

template <bool RELU, bool ROUND_OUT>
__global__ __launch_bounds__(256, 2) void gemm_bf16_kernel(
    const __nv_bfloat16* __restrict__ Ahi, const __nv_bfloat16* __restrict__ Alo,
    const __nv_bfloat16* __restrict__ Whi, const __nv_bfloat16* __restrict__ Wlo,
    const float* __restrict__ bias, float* __restrict__ Cmat,
    int Mdim, int Ndim, int Kdim)
{
    extern __shared__ unsigned smu[];
    unsigned* sAh = smu;
    unsigned* sAl = sAh + 2 * GPLW;
    unsigned* sBh = sAl + 2 * GPLW;
    unsigned* sBl = sBh + 2 * GPLW;

    const int tid  = threadIdx.x;
    const int lane = tid & 31;
    const int wid  = tid >> 5;
    const int wm   = (wid & 3) * 32;
    const int wn   = (wid >> 2) * 64;
    const int g    = lane >> 2;
    const int tg   = lane & 3;

    const int m0 = blockIdx.y * 128;
    const int n0 = blockIdx.x * 128;
    const int NK = Kdim >> 5;          // k32 tiles

    float acc[2][8][4];
#pragma unroll
    for (int im = 0; im < 2; im++)
#pragma unroll
        for (int in = 0; in < 8; in++)
#pragma unroll
            for (int e = 0; e < 4; e++) acc[im][in][e] = 0.f;

    // per stage/plane: 128 rows x 32 elts x 2B = 8KB = 512 16B-chunks.
    // Global layout already permuted; chunks copy linearly.
    auto load_stage = [&](int kt, int st) {
        const int k0 = kt << 5;
#pragma unroll
        for (int i = 0; i < 8; i++) {
            int cc = tid + (i & 1) * 256;   // 0..511
            int r  = cc >> 2;               // 0..127
            int j  = cc & 3;                // 16B chunk = 8 elts = 4 words
            unsigned* dstw;
            const __nv_bfloat16* src;
            if ((i >> 1) == 0) {
                dstw = &sAh[st * GPLW + r * GST + 4 * j];
                src  = Ahi + (size_t)(m0 + r) * Kdim + k0 + 8 * j;
            } else if ((i >> 1) == 1) {
                dstw = &sAl[st * GPLW + r * GST + 4 * j];
                src  = Alo + (size_t)(m0 + r) * Kdim + k0 + 8 * j;
            } else if ((i >> 1) == 2) {
                dstw = &sBh[st * GPLW + r * GST + 4 * j];
                src  = Whi + (size_t)(n0 + r) * Kdim + k0 + 8 * j;
            } else {
                dstw = &sBl[st * GPLW + r * GST + 4 * j];
                src  = Wlo + (size_t)(n0 + r) * Kdim + k0 + 8 * j;
            }
            cp_async16(dstw, src);
        }
        asm volatile("cp.async.commit_group;" ::: "memory");
    };

    load_stage(0, 0);

    for (int kt = 0; kt < NK; kt++) {
        const int cur = kt & 1;
        if (kt + 1 < NK) {
            load_stage(kt + 1, (kt + 1) & 1);
            asm volatile("cp.async.wait_group 1;" ::: "memory");
        } else {
            asm volatile("cp.async.wait_group 0;" ::: "memory");
        }
        __syncthreads();

        const unsigned* pAh = sAh + cur * GPLW;
        const unsigned* pAl = sAl + cur * GPLW;
        const unsigned* pBh = sBh + cur * GPLW;
        const unsigned* pBl = sBl + cur * GPLW;

#pragma unroll
        for (int kw = 0; kw < 16; kw += 8) {   // two k16 steps per tile
            // A fragment pairs: one LDS.64 = (a0,a2) for row r, (a1,a3) row r+8
            uint2 ahp[2][2], alp[2][2];
#pragma unroll
            for (int im = 0; im < 2; im++) {
                int r = wm + im * 16 + g;
                ahp[im][0] = *(const uint2*)&pAh[r * GST + kw + 2 * tg];
                ahp[im][1] = *(const uint2*)&pAh[(r + 8) * GST + kw + 2 * tg];
                alp[im][0] = *(const uint2*)&pAl[r * GST + kw + 2 * tg];
                alp[im][1] = *(const uint2*)&pAl[(r + 8) * GST + kw + 2 * tg];
            }
#pragma unroll
            for (int in = 0; in < 8; in++) {
                int c = wn + in * 8 + g;
                uint2 bh = *(const uint2*)&pBh[c * GST + kw + 2 * tg];
                uint2 bl = *(const uint2*)&pBl[c * GST + kw + 2 * tg];
#pragma unroll
                for (int im = 0; im < 2; im++) {
                    float* d = acc[im][in];
                    mma_bf16(d[0], d[1], d[2], d[3],
                             ahp[im][0].x, ahp[im][1].x,
                             ahp[im][0].y, ahp[im][1].y,
                             bh.x, bh.y);
                    mma_bf16(d[0], d[1], d[2], d[3],
                             ahp[im][0].x, ahp[im][1].x,
                             ahp[im][0].y, ahp[im][1].y,
                             bl.x, bl.y);
                    mma_bf16(d[0], d[1], d[2], d[3],
                             alp[im][0].x, alp[im][1].x,
                             alp[im][0].y, alp[im][1].y,
                             bh.x, bh.y);
                }
            }
        }
        __syncthreads();
    }

#pragma unroll
    for (int in = 0; in < 8; in++) {
        int col = n0 + wn + in * 8 + 2 * tg;
        float2 bz = *(const float2*)&bias[col];
#pragma unroll
        for (int im = 0; im < 2; im++) {
            int row = m0 + wm + im * 16 + g;
            float v0 = acc[im][in][0] + bz.x;
            float v1 = acc[im][in][1] + bz.y;
            float v2 = acc[im][in][2] + bz.x;
            float v3 = acc[im][in][3] + bz.y;
            if (RELU) {
                v0 = fmaxf(v0, 0.f); v1 = fmaxf(v1, 0.f);
                v2 = fmaxf(v2, 0.f); v3 = fmaxf(v3, 0.f);
            }
            if (ROUND_OUT) {
                v0 = __uint_as_float(f2tf32(v0));
                v1 = __uint_as_float(f2tf32(v1));
                v2 = __uint_as_float(f2tf32(v2));
                v3 = __uint_as_float(f2tf32(v3));
            }
            float2 p0; p0.x = v0; p0.y = v1;
            float2 p1; p1.x = v2; p1.y = v3;
            *(float2*)&Cmat[(size_t)row * Ndim + col] = p0;
            *(float2*)&Cmat[(size_t)(row + 8) * Ndim + col] = p1;
        }
    }
}

// ---------------------------------------------------------------------------
// Chunked fused attention (R9, known-good): block = (b, h, 64 q rows),
// 64-col chunks, tf32 mma, no max-pass. Only change: y bf16 hi/lo stores
// use the permuted word layout (consumed by the proj GEMM).
// ---------------------------------------------------------------------------
#define BMq  64
#define KSP2 68
#define W2S  72
#define VSS  72
#define PSS  68

__global__ __launch_bounds__(256, 2) void attn2_kernel(
    const float* __restrict__ gk, const float* __restrict__ gv,
    const float* __restrict__ w2r, const float* __restrict__ b2,
    __nv_bfloat16* __restrict__ yhi, __nv_bfloat16* __restrict__ ylo)
{
    extern __shared__ float sm[];
    float* ks    = sm;
    float* w2s   = ks + 64 * KSP2;
    float* vs    = w2s + 2 * 64 * W2S;
    float* ps    = vs + 2 * 64 * VSS;
    float* dpart = ps + 64 * PSS;
    float* denom = dpart + 8 * 64;

    const int t0  = blockIdx.x * BMq;
    const int h   = blockIdx.y;
    const int bb_ = blockIdx.z;
    const int tid = threadIdx.x;
    const int lane = tid & 31;
    const int wid  = tid >> 5;
    const int g    = lane >> 2;
    const int tg   = lane & 3;

    const int nch = (t0 >> 6) + 1;

    auto stage = [&](int c, int buf) {
        const int c0 = c << 6;
        float* w2d = w2s + buf * 64 * W2S;
        float* vsd = vs + buf * 64 * VSS;
        const float* w2g = w2r + (size_t)h * HDq * Mq + c0;
        const float* vg  = gv + (size_t)bb_ * Tq * Cq + (size_t)c0 * Cq + h * HDq;
#pragma unroll
        for (int i = 0; i < 4; i++) {
            int cc = tid + i * 256;
            int d  = cc >> 4;
            int m4 = (cc & 15) << 2;
            cp_async16(&w2d[d * W2S + m4], &w2g[(size_t)d * Mq + m4]);
        }
#pragma unroll
        for (int i = 0; i < 4; i++) {
            int cc = tid + i * 256;
            int l  = cc >> 4;
            int d4 = (cc & 15) << 2;
            cp_async16(&vsd[l * VSS + d4], &vg[(size_t)l * Cq + d4]);
        }
        asm volatile("cp.async.commit_group;" ::: "memory");
    };

    {
#pragma unroll
        for (int i = 0; i < 4; i++) {
            int cc = tid + i * 256;
            int r  = cc >> 4;
            int d4 = (cc & 15) << 2;
            cp_async16(&ks[r * KSP2 + d4],
                       &gk[(size_t)(bb_ * Tq + t0 + r) * Cq + h * HDq + d4]);
        }
        stage(0, 0);
    }

    float o[4][4];
    float dp[4][2];
#pragma unroll
    for (int im = 0; im < 4; im++) {
#pragma unroll
        for (int e = 0; e < 4; e++) o[im][e] = 0.f;
        dp[im][0] = 0.f; dp[im][1] = 0.f;
    }

    for (int c = 0; c < nch; c++) {
        const int buf = c & 1;
        if (c + 1 < nch) {
            stage(c + 1, (c + 1) & 1);
            asm volatile("cp.async.wait_group 1;" ::: "memory");
        } else {
            asm volatile("cp.async.wait_group 0;" ::: "memory");
        }
        __syncthreads();

        const float* w2c = w2s + buf * 64 * W2S;
        float d[4][4];
#pragma unroll
        for (int im = 0; im < 4; im++) {
#pragma unroll
            for (int e = 0; e < 4; e++) d[im][e] = 0.f;
        }

#pragma unroll
        for (int kf = 0; kf < 8; kf++) {
            const int cc = wid * 8 + g;
            unsigned b0 = __float_as_uint(w2c[(kf * 8 + tg) * W2S + cc]);
            unsigned b1 = __float_as_uint(w2c[(kf * 8 + tg + 4) * W2S + cc]);
#pragma unroll
            for (int im = 0; im < 4; im++) {
                int r = im * 16 + g;
                unsigned a0 = __float_as_uint(ks[r * KSP2 + kf * 8 + tg]);
                unsigned a1 = __float_as_uint(ks[(r + 8) * KSP2 + kf * 8 + tg]);
                unsigned a2 = __float_as_uint(ks[r * KSP2 + kf * 8 + tg + 4]);
                unsigned a3 = __float_as_uint(ks[(r + 8) * KSP2 + kf * 8 + tg + 4]);
                mma_tf32(d[im][0], d[im][1], d[im][2], d[im][3],
                         a0, a1, a2, a3, b0, b1);
            }
        }

        {
            const int colb = (c << 6) + wid * 8 + 2 * tg;
            float2 bz = *(const float2*)&b2[colb];
            const int loc = wid * 8 + 2 * tg;
#pragma unroll
            for (int im = 0; im < 4; im++) {
                const int r1 = t0 + im * 16 + g;
                const int r2 = r1 + 8;
                float s0 = d[im][0] + bz.x;
                float s1 = d[im][1] + bz.y;
                float s2 = d[im][2] + bz.x;
                float s3 = d[im][3] + bz.y;
                float e0 = (colb     <= r1) ? __expf(s0) : 0.f;
                float e1 = (colb + 1 <= r1) ? __expf(s1) : 0.f;
                float e2 = (colb     <= r2) ? __expf(s2) : 0.f;
                float e3 = (colb + 1 <= r2) ? __expf(s3) : 0.f;
                dp[im][0] += e0 + e1;
                dp[im][1] += e2 + e3;
                float2 p0, p1;
                p0.x = __uint_as_float(f2tf32(e0));
                p0.y = __uint_as_float(f2tf32(e1));
                p1.x = __uint_as_float(f2tf32(e2));
                p1.y = __uint_as_float(f2tf32(e3));
                *(float2*)&ps[(im * 16 + g) * PSS + loc] = p0;
                *(float2*)&ps[(im * 16 + 8 + g) * PSS + loc] = p1;
            }
        }
        __syncthreads();

        const float* vc = vs + buf * 64 * VSS;
#pragma unroll
        for (int kf = 0; kf < 8; kf++) {
            const int l0 = kf * 8;
            unsigned b0 = __float_as_uint(vc[(l0 + tg) * VSS + wid * 8 + g]);
            unsigned b1 = __float_as_uint(vc[(l0 + tg + 4) * VSS + wid * 8 + g]);
#pragma unroll
            for (int im = 0; im < 4; im++) {
                int r = im * 16 + g;
                unsigned a0 = __float_as_uint(ps[r * PSS + l0 + tg]);
                unsigned a1 = __float_as_uint(ps[(r + 8) * PSS + l0 + tg]);
                unsigned a2 = __float_as_uint(ps[r * PSS + l0 + tg + 4]);
                unsigned a3 = __float_as_uint(ps[(r + 8) * PSS + l0 + tg + 4]);
                mma_tf32(o[im][0], o[im][1], o[im][2], o[im][3],
                         a0, a1, a2, a3, b0, b1);
            }
        }
        __syncthreads();
    }

#pragma unroll
    for (int im = 0; im < 4; im++) {
#pragma unroll
        for (int hf = 0; hf < 2; hf++) {
            float v = dp[im][hf];
            v += __shfl_xor_sync(0xffffffffu, v, 1);
            v += __shfl_xor_sync(0xffffffffu, v, 2);
            dp[im][hf] = v;
        }
    }
    if (tg == 0) {
#pragma unroll
        for (int im = 0; im < 4; im++) {
            dpart[wid * 64 + im * 16 + g]     = dp[im][0];
            dpart[wid * 64 + im * 16 + 8 + g] = dp[im][1];
        }
    }
    __syncthreads();
    if (tid < 64) {
        float s = 0.f;
#pragma unroll
        for (int w = 0; w < 8; w++) s += dpart[w * 64 + tid];
        denom[tid] = 1.f / s;
    }
    __syncthreads();

    // ---- output: y as bf16 hi/lo planes in the PERMUTED word layout ----
#pragma unroll
    for (int im = 0; im < 4; im++) {
        const int r = im * 16 + g;
        const float iv1 = denom[r];
        const float iv2 = denom[r + 8];
        float y0 = o[im][0] * iv1, y1 = o[im][1] * iv1;
        float y2 = o[im][2] * iv2, y3 = o[im][3] * iv2;
        __nv_bfloat16 h0, l0, h1, l1, h2, l2, h3, l3;
        bf16_split(y0, h0, l0); bf16_split(y1, h1, l1);
        bf16_split(y2, h2, l2); bf16_split(y3, h3, l3);
        size_t off1 = (size_t)(bb_ * Tq + t0 + r) * Cq + h * HDq + wid * 8 + 2 * tg;
        size_t off2 = (size_t)(bb_ * Tq + t0 + r + 8) * Cq + h * HDq + wid * 8 + 2 * tg;
        size_t e1 = perm_word(off1 >> 1) << 1;
        size_t e2 = perm_word(off2 >> 1) << 1;
        __nv_bfloat162 ph0; ph0.x = h0; ph0.y = h1;
        __nv_bfloat162 pl0; pl0.x = l0; pl0.y = l1;
        __nv_bfloat162 ph1; ph1.x = h2; ph1.y = h3;
        __nv_bfloat162 pl1; pl1.x = l2; pl1.y = l3;
        *(__nv_bfloat162*)&yhi[e1] = ph0;
        *(__nv_bfloat162*)&ylo[e1] = pl0;
        *(__nv_bfloat162*)&yhi[e2] = ph1;
        *(__nv_bfloat162*)&ylo[e2] = pl1;
    }
}

// ---------------------------------------------------------------------------
extern "C" void kernel_launch(void* const* d_in, const int* in_sizes, int n_in,
                              void* d_out, int out_size)
{
    const float* x       = (const float*)d_in[0];
    const float* w1_w    = (const float*)d_in[1];
    const float* w1_b    = (const float*)d_in[2];
    const float* w2      = (const float*)d_in[3];
    const float* b2      = (const float*)d_in[4];
    const float* value_w = (const float*)d_in[5];
    const float* value_b = (const float*)d_in[6];
    const float* proj_w  = (const float*)d_in[7];
    const float* proj_b  = (const float*)d_in[8];
    float* out = (float*)d_out;

    float *pk, *pv, *pw2r;
    __nv_bfloat16 *pahi, *palo, *pwhi, *pwlo;
    cudaGetSymbolAddress((void**)&pk,   g_k);
    cudaGetSymbolAddress((void**)&pv,   g_v);
    cudaGetSymbolAddress((void**)&pw2r, g_w2r);
    cudaGetSymbolAddress((void**)&pahi, g_ahi);
    cudaGetSymbolAddress((void**)&palo, g_alo);
    cudaGetSymbolAddress((void**)&pwhi, g_whi);
    cudaGetSymbolAddress((void**)&pwlo, g_wlo);

    const int SMEM_GEMM = 8 * GPLW * (int)sizeof(unsigned);           // 96 KB
    const int SMEM_ATTN = (64 * KSP2 + 2 * 64 * W2S + 2 * 64 * VSS +
                           64 * PSS + 8 * 64 + 64) * (int)sizeof(float);
    cudaFuncSetAttribute(gemm_bf16_kernel<true, true>,
                         cudaFuncAttributeMaxDynamicSharedMemorySize, SMEM_GEMM);
    cudaFuncSetAttribute(gemm_bf16_kernel<false, true>,
                         cudaFuncAttributeMaxDynamicSharedMemorySize, SMEM_GEMM);
    cudaFuncSetAttribute(gemm_bf16_kernel<false, false>,
                         cudaFuncAttributeMaxDynamicSharedMemorySize, SMEM_GEMM);
    cudaFuncSetAttribute(attn2_kernel,
                         cudaFuncAttributeMaxDynamicSharedMemorySize, SMEM_ATTN);

    const int Mrows = Bq * Tq;                 // 4096
    const int NACT4 = Mrows * Cq / 4;
    const int NW4   = Cq * Cq / 4;
    const int NW24  = Hq * HDq * Mq / 4;
    dim3 gemm_grid(Cq / 128, Mrows / 128);     // (8, 32)

    // prep: split x (bf16 hi/lo, permuted), round w2 (tf32)
    split_bf16_kernel<<<(NACT4 + 255) / 256, 256>>>(
        (const float4*)x, (__nv_bfloat162*)pahi, (__nv_bfloat162*)palo, NACT4);
    round_kernel<<<(NW24 + 255) / 256, 256>>>(
        (const float4*)w2, (float4*)pw2r, NW24);

    // k = relu(x @ w1^T + b1), tf32-rounded output
    split_bf16_kernel<<<(NW4 + 255) / 256, 256>>>(
        (const float4*)w1_w, (__nv_bfloat162*)pwhi, (__nv_bfloat162*)pwlo, NW4);
    gemm_bf16_kernel<true, true><<<gemm_grid, 256, SMEM_GEMM>>>(
        pahi, palo, pwhi, pwlo, w1_b, pk, Mrows, Cq, Cq);

    // v = x @ value^T + vb, tf32-rounded output
    split_bf16_kernel<<<(NW4 + 255) / 256, 256>>>(
        (const float4*)value_w, (__nv_bfloat162*)pwhi, (__nv_bfloat162*)pwlo, NW4);
    gemm_bf16_kernel<false, true><<<gemm_grid, 256, SMEM_GEMM>>>(
        pahi, palo, pwhi, pwlo, value_b, pv, Mrows, Cq, Cq);

    // attention: writes y bf16 hi/lo planes in permuted layout
    dim3 agrid(Tq / BMq, Hq, Bq);              // (32, 16, 2)
    attn2_kernel<<<agrid, 256, SMEM_ATTN>>>(pk, pv, pw2r, b2, pahi, palo);

    // out = y @ proj^T + pb (fp32 output)
    split_bf16_kernel<<<(NW4 + 255) / 256, 256>>>(
        (const float4*)proj_w, (__nv_bfloat162*)pwhi, (__nv_bfloat162*)pwlo, NW4);
    gemm_bf16_kernel<false, false><<<gemm_grid, 256, SMEM_GEMM>>>(
        pahi, palo, pwhi, pwlo, proj_b, out, Mrows, Cq, Cq);
}

// round 14
// speedup vs baseline: 1.0340x; 1.0340x over previous
#include <cuda_runtime.h>
#include <cuda_bf16.h>
#include <math.h>

// Problem constants
#define Bq   2
#define Tq   2048
#define Cq   1024
#define Hq   16
#define HDq  64
#define Mq   2048

// Scratch (allocation-free rule: __device__ globals)
__device__ float         g_k[Bq * Tq * Cq];    // relu(x@w1^T+b1), tf32-rounded
__device__ float         g_v[Bq * Tq * Cq];    // x@value^T+vb, tf32-rounded
__device__ __nv_bfloat16 g_ahi[Bq * Tq * Cq];  // activation hi plane (x, then y)
__device__ __nv_bfloat16 g_alo[Bq * Tq * Cq];  // activation lo plane
__device__ __nv_bfloat16 g_w1hi[Cq * Cq];      // w1 hi plane
__device__ __nv_bfloat16 g_w1lo[Cq * Cq];      // w1 lo plane
__device__ __nv_bfloat16 g_vwhi[Cq * Cq];      // value_w hi plane
__device__ __nv_bfloat16 g_vwlo[Cq * Cq];      // value_w lo plane
__device__ __nv_bfloat16 g_pwhi[Cq * Cq];      // proj_w hi plane
__device__ __nv_bfloat16 g_pwlo[Cq * Cq];      // proj_w lo plane
__device__ float         g_w2r[Hq * HDq * Mq]; // w2 tf32-rounded

// ---------------------------------------------------------------------------
// helpers
// ---------------------------------------------------------------------------
__device__ __forceinline__ unsigned f2tf32(float x) {
    unsigned u;
    asm("cvt.rna.tf32.f32 %0, %1;" : "=r"(u) : "f"(x));
    return u;
}

__device__ __forceinline__ void mma_tf32(
    float& d0, float& d1, float& d2, float& d3,
    unsigned a0, unsigned a1, unsigned a2, unsigned a3,
    unsigned b0, unsigned b1)
{
    asm volatile(
        "mma.sync.aligned.m16n8k8.row.col.f32.tf32.tf32.f32 "
        "{%0,%1,%2,%3}, {%4,%5,%6,%7}, {%8,%9}, {%0,%1,%2,%3};"
        : "+f"(d0), "+f"(d1), "+f"(d2), "+f"(d3)
        : "r"(a0), "r"(a1), "r"(a2), "r"(a3), "r"(b0), "r"(b1));
}

__device__ __forceinline__ void mma_bf16(
    float& d0, float& d1, float& d2, float& d3,
    unsigned a0, unsigned a1, unsigned a2, unsigned a3,
    unsigned b0, unsigned b1)
{
    asm volatile(
        "mma.sync.aligned.m16n8k16.row.col.f32.bf16.bf16.f32 "
        "{%0,%1,%2,%3}, {%4,%5,%6,%7}, {%8,%9}, {%0,%1,%2,%3};"
        : "+f"(d0), "+f"(d1), "+f"(d2), "+f"(d3)
        : "r"(a0), "r"(a1), "r"(a2), "r"(a3), "r"(b0), "r"(b1));
}

__device__ __forceinline__ void cp_async16(void* s, const void* g) {
    unsigned sa = (unsigned)__cvta_generic_to_shared(s);
    asm volatile("cp.async.cg.shared.global [%0], [%1], 16;" :: "r"(sa), "l"(g));
}

__device__ __forceinline__ void bf16_split(float v, __nv_bfloat16& h, __nv_bfloat16& l) {
    h = __float2bfloat16_rn(v);
    l = __float2bfloat16_rn(v - __bfloat162float(h));
}

// ---------------------------------------------------------------------------
// Fused prep kernel: one launch covers all 5 prep jobs (flat grid, ranges
// are compile-time). Job layout (in float4 items):
//   [0, NACT4)                      : split x -> ahi/alo
//   [NACT4, +NW4)                   : split w1
//   [NACT4+NW4, +NW4)               : split value_w
//   [NACT4+2*NW4, +NW4)             : split proj_w
//   [NACT4+3*NW4, +NW24)            : round w2 -> w2r
// ---------------------------------------------------------------------------
#define NACT4 ((Bq * Tq * Cq) / 4)        // 1048576
#define NW4   ((Cq * Cq) / 4)             // 262144
#define NW24  ((Hq * HDq * Mq) / 4)       // 524288
#define PREP_TOTAL (NACT4 + 3 * NW4 + NW24)   // 2359296 (divisible by 256)

__device__ __forceinline__ void split4_store(
    float4 v, __nv_bfloat162* hi, __nv_bfloat162* lo, int i)
{
    __nv_bfloat16 hx, lx, hy, ly, hz, lz, hw, lw;
    bf16_split(v.x, hx, lx);
    bf16_split(v.y, hy, ly);
    bf16_split(v.z, hz, lz);
    bf16_split(v.w, hw, lw);
    __nv_bfloat162 h0; h0.x = hx; h0.y = hy;
    __nv_bfloat162 h1; h1.x = hz; h1.y = hw;
    __nv_bfloat162 l0; l0.x = lx; l0.y = ly;
    __nv_bfloat162 l1; l1.x = lz; l1.y = lw;
    hi[2 * i] = h0; hi[2 * i + 1] = h1;
    lo[2 * i] = l0; lo[2 * i + 1] = l1;
}

__global__ __launch_bounds__(256) void prep_kernel(
    const float4* __restrict__ x,  const float4* __restrict__ w1,
    const float4* __restrict__ vw, const float4* __restrict__ pw,
    const float4* __restrict__ w2,
    __nv_bfloat162* __restrict__ ahi,  __nv_bfloat162* __restrict__ alo,
    __nv_bfloat162* __restrict__ w1hi, __nv_bfloat162* __restrict__ w1lo,
    __nv_bfloat162* __restrict__ vwhi, __nv_bfloat162* __restrict__ vwlo,
    __nv_bfloat162* __restrict__ pwhi, __nv_bfloat162* __restrict__ pwlo,
    float4* __restrict__ w2r)
{
    int gi = blockIdx.x * 256 + threadIdx.x;
    if (gi < NACT4) {
        split4_store(x[gi], ahi, alo, gi);
    } else if (gi < NACT4 + NW4) {
        int i = gi - NACT4;
        split4_store(w1[i], w1hi, w1lo, i);
    } else if (gi < NACT4 + 2 * NW4) {
        int i = gi - (NACT4 + NW4);
        split4_store(vw[i], vwhi, vwlo, i);
    } else if (gi < NACT4 + 3 * NW4) {
        int i = gi - (NACT4 + 2 * NW4);
        split4_store(pw[i], pwhi, pwlo, i);
    } else {
        int i = gi - (NACT4 + 3 * NW4);
        float4 v = w2[i];
        float4 o;
        o.x = __uint_as_float(f2tf32(v.x));
        o.y = __uint_as_float(f2tf32(v.y));
        o.z = __uint_as_float(f2tf32(v.z));
        o.w = __uint_as_float(f2tf32(v.w));
        w2r[i] = o;
    }
}

// ---------------------------------------------------------------------------
// Dense GEMM via 3x bf16 hi/lo mma (R9, proven): cp.async 2-stage, 2 CTAs/SM
//   C[M,N] = act(A[M,K] @ W[N,K]^T + bias[N])
// ---------------------------------------------------------------------------
#define ST   20
#define PLW  2560   // 128 * ST words per plane-stage

template <bool RELU, bool ROUND_OUT>
__global__ __launch_bounds__(256, 2) void gemm_bf16_kernel(
    const __nv_bfloat16* __restrict__ Ahi, const __nv_bfloat16* __restrict__ Alo,
    const __nv_bfloat16* __restrict__ Whi, const __nv_bfloat16* __restrict__ Wlo,
    const float* __restrict__ bias, float* __restrict__ Cmat,
    int Mdim, int Ndim, int Kdim)
{
    extern __shared__ unsigned smu[];
    unsigned* sAh = smu;
    unsigned* sAl = sAh + 2 * PLW;
    unsigned* sBh = sAl + 2 * PLW;
    unsigned* sBl = sBh + 2 * PLW;

    const int tid  = threadIdx.x;
    const int lane = tid & 31;
    const int wid  = tid >> 5;
    const int wm   = (wid & 3) * 32;
    const int wn   = (wid >> 2) * 64;
    const int g    = lane >> 2;
    const int tg   = lane & 3;

    const int m0 = blockIdx.y * 128;
    const int n0 = blockIdx.x * 128;
    const int NK = Kdim >> 5;          // k32 tiles

    float acc[2][8][4];
#pragma unroll
    for (int im = 0; im < 2; im++)
#pragma unroll
        for (int in = 0; in < 8; in++)
#pragma unroll
            for (int e = 0; e < 4; e++) acc[im][in][e] = 0.f;

    auto load_stage = [&](int kt, int st) {
        const int k0 = kt << 5;
#pragma unroll
        for (int i = 0; i < 8; i++) {
            int cc = tid + (i & 1) * 256;   // 0..511
            int r  = cc >> 2;               // 0..127
            int j  = cc & 3;                // 16B chunk = 8 elts = 4 words
            if ((i >> 1) == 0)
                cp_async16(&sAh[st * PLW + r * ST + 4 * j],
                           &Ahi[(size_t)(m0 + r) * Kdim + k0 + 8 * j]);
            else if ((i >> 1) == 1)
                cp_async16(&sAl[st * PLW + r * ST + 4 * j],
                           &Alo[(size_t)(m0 + r) * Kdim + k0 + 8 * j]);
            else if ((i >> 1) == 2)
                cp_async16(&sBh[st * PLW + r * ST + 4 * j],
                           &Whi[(size_t)(n0 + r) * Kdim + k0 + 8 * j]);
            else
                cp_async16(&sBl[st * PLW + r * ST + 4 * j],
                           &Wlo[(size_t)(n0 + r) * Kdim + k0 + 8 * j]);
        }
        asm volatile("cp.async.commit_group;" ::: "memory");
    };

    load_stage(0, 0);

    for (int kt = 0; kt < NK; kt++) {
        const int cur = kt & 1;
        if (kt + 1 < NK) {
            load_stage(kt + 1, (kt + 1) & 1);
            asm volatile("cp.async.wait_group 1;" ::: "memory");
        } else {
            asm volatile("cp.async.wait_group 0;" ::: "memory");
        }
        __syncthreads();

        const unsigned* pAh = sAh + cur * PLW;
        const unsigned* pAl = sAl + cur * PLW;
        const unsigned* pBh = sBh + cur * PLW;
        const unsigned* pBl = sBl + cur * PLW;

#pragma unroll
        for (int kw = 0; kw < 16; kw += 8) {   // two k16 steps per tile
            unsigned ah[2][4], al[2][4];
#pragma unroll
            for (int im = 0; im < 2; im++) {
                int r = wm + im * 16 + g;
                ah[im][0] = pAh[r * ST + kw + tg];
                ah[im][1] = pAh[(r + 8) * ST + kw + tg];
                ah[im][2] = pAh[r * ST + kw + tg + 4];
                ah[im][3] = pAh[(r + 8) * ST + kw + tg + 4];
                al[im][0] = pAl[r * ST + kw + tg];
                al[im][1] = pAl[(r + 8) * ST + kw + tg];
                al[im][2] = pAl[r * ST + kw + tg + 4];
                al[im][3] = pAl[(r + 8) * ST + kw + tg + 4];
            }
#pragma unroll
            for (int in = 0; in < 8; in++) {
                int c = wn + in * 8 + g;
                unsigned bh0 = pBh[c * ST + kw + tg];
                unsigned bh1 = pBh[c * ST + kw + tg + 4];
                unsigned bl0 = pBl[c * ST + kw + tg];
                unsigned bl1 = pBl[c * ST + kw + tg + 4];
#pragma unroll
                for (int im = 0; im < 2; im++) {
                    float* d = acc[im][in];
                    mma_bf16(d[0], d[1], d[2], d[3],
                             ah[im][0], ah[im][1], ah[im][2], ah[im][3],
                             bh0, bh1);
                    mma_bf16(d[0], d[1], d[2], d[3],
                             ah[im][0], ah[im][1], ah[im][2], ah[im][3],
                             bl0, bl1);
                    mma_bf16(d[0], d[1], d[2], d[3],
                             al[im][0], al[im][1], al[im][2], al[im][3],
                             bh0, bh1);
                }
            }
        }
        __syncthreads();
    }

#pragma unroll
    for (int in = 0; in < 8; in++) {
        int col = n0 + wn + in * 8 + 2 * tg;
        float2 bz = *(const float2*)&bias[col];
#pragma unroll
        for (int im = 0; im < 2; im++) {
            int row = m0 + wm + im * 16 + g;
            float v0 = acc[im][in][0] + bz.x;
            float v1 = acc[im][in][1] + bz.y;
            float v2 = acc[im][in][2] + bz.x;
            float v3 = acc[im][in][3] + bz.y;
            if (RELU) {
                v0 = fmaxf(v0, 0.f); v1 = fmaxf(v1, 0.f);
                v2 = fmaxf(v2, 0.f); v3 = fmaxf(v3, 0.f);
            }
            if (ROUND_OUT) {
                v0 = __uint_as_float(f2tf32(v0));
                v1 = __uint_as_float(f2tf32(v1));
                v2 = __uint_as_float(f2tf32(v2));
                v3 = __uint_as_float(f2tf32(v3));
            }
            float2 p0; p0.x = v0; p0.y = v1;
            float2 p1; p1.x = v2; p1.y = v3;
            *(float2*)&Cmat[(size_t)row * Ndim + col] = p0;
            *(float2*)&Cmat[(size_t)(row + 8) * Ndim + col] = p1;
        }
    }
}

// ---------------------------------------------------------------------------
// Chunked fused attention (R9, proven): block = (b, h, 64 q rows), 64-col
// chunks, tf32 mma, no max-pass; y emitted as bf16 hi/lo planes (linear).
// ---------------------------------------------------------------------------
#define BMq  64
#define KSP2 68
#define W2S  72
#define VSS  72
#define PSS  68

__global__ __launch_bounds__(256, 2) void attn2_kernel(
    const float* __restrict__ gk, const float* __restrict__ gv,
    const float* __restrict__ w2r, const float* __restrict__ b2,
    __nv_bfloat16* __restrict__ yhi, __nv_bfloat16* __restrict__ ylo)
{
    extern __shared__ float sm[];
    float* ks    = sm;
    float* w2s   = ks + 64 * KSP2;
    float* vs    = w2s + 2 * 64 * W2S;
    float* ps    = vs + 2 * 64 * VSS;
    float* dpart = ps + 64 * PSS;
    float* denom = dpart + 8 * 64;

    const int t0  = blockIdx.x * BMq;
    const int h   = blockIdx.y;
    const int bb_ = blockIdx.z;
    const int tid = threadIdx.x;
    const int lane = tid & 31;
    const int wid  = tid >> 5;
    const int g    = lane >> 2;
    const int tg   = lane & 3;

    const int nch = (t0 >> 6) + 1;

    auto stage = [&](int c, int buf) {
        const int c0 = c << 6;
        float* w2d = w2s + buf * 64 * W2S;
        float* vsd = vs + buf * 64 * VSS;
        const float* w2g = w2r + (size_t)h * HDq * Mq + c0;
        const float* vg  = gv + (size_t)bb_ * Tq * Cq + (size_t)c0 * Cq + h * HDq;
#pragma unroll
        for (int i = 0; i < 4; i++) {
            int cc = tid + i * 256;
            int d  = cc >> 4;
            int m4 = (cc & 15) << 2;
            cp_async16(&w2d[d * W2S + m4], &w2g[(size_t)d * Mq + m4]);
        }
#pragma unroll
        for (int i = 0; i < 4; i++) {
            int cc = tid + i * 256;
            int l  = cc >> 4;
            int d4 = (cc & 15) << 2;
            cp_async16(&vsd[l * VSS + d4], &vg[(size_t)l * Cq + d4]);
        }
        asm volatile("cp.async.commit_group;" ::: "memory");
    };

    {
#pragma unroll
        for (int i = 0; i < 4; i++) {
            int cc = tid + i * 256;
            int r  = cc >> 4;
            int d4 = (cc & 15) << 2;
            cp_async16(&ks[r * KSP2 + d4],
                       &gk[(size_t)(bb_ * Tq + t0 + r) * Cq + h * HDq + d4]);
        }
        stage(0, 0);
    }

    float o[4][4];
    float dp[4][2];
#pragma unroll
    for (int im = 0; im < 4; im++) {
#pragma unroll
        for (int e = 0; e < 4; e++) o[im][e] = 0.f;
        dp[im][0] = 0.f; dp[im][1] = 0.f;
    }

    for (int c = 0; c < nch; c++) {
        const int buf = c & 1;
        if (c + 1 < nch) {
            stage(c + 1, (c + 1) & 1);
            asm volatile("cp.async.wait_group 1;" ::: "memory");
        } else {
            asm volatile("cp.async.wait_group 0;" ::: "memory");
        }
        __syncthreads();

        const float* w2c = w2s + buf * 64 * W2S;
        float d[4][4];
#pragma unroll
        for (int im = 0; im < 4; im++) {
#pragma unroll
            for (int e = 0; e < 4; e++) d[im][e] = 0.f;
        }

#pragma unroll
        for (int kf = 0; kf < 8; kf++) {
            const int cc = wid * 8 + g;
            unsigned b0 = __float_as_uint(w2c[(kf * 8 + tg) * W2S + cc]);
            unsigned b1 = __float_as_uint(w2c[(kf * 8 + tg + 4) * W2S + cc]);
#pragma unroll
            for (int im = 0; im < 4; im++) {
                int r = im * 16 + g;
                unsigned a0 = __float_as_uint(ks[r * KSP2 + kf * 8 + tg]);
                unsigned a1 = __float_as_uint(ks[(r + 8) * KSP2 + kf * 8 + tg]);
                unsigned a2 = __float_as_uint(ks[r * KSP2 + kf * 8 + tg + 4]);
                unsigned a3 = __float_as_uint(ks[(r + 8) * KSP2 + kf * 8 + tg + 4]);
                mma_tf32(d[im][0], d[im][1], d[im][2], d[im][3],
                         a0, a1, a2, a3, b0, b1);
            }
        }

        {
            const int colb = (c << 6) + wid * 8 + 2 * tg;
            float2 bz = *(const float2*)&b2[colb];
            const int loc = wid * 8 + 2 * tg;
#pragma unroll
            for (int im = 0; im < 4; im++) {
                const int r1 = t0 + im * 16 + g;
                const int r2 = r1 + 8;
                float s0 = d[im][0] + bz.x;
                float s1 = d[im][1] + bz.y;
                float s2 = d[im][2] + bz.x;
                float s3 = d[im][3] + bz.y;
                float e0 = (colb     <= r1) ? __expf(s0) : 0.f;
                float e1 = (colb + 1 <= r1) ? __expf(s1) : 0.f;
                float e2 = (colb     <= r2) ? __expf(s2) : 0.f;
                float e3 = (colb + 1 <= r2) ? __expf(s3) : 0.f;
                dp[im][0] += e0 + e1;
                dp[im][1] += e2 + e3;
                float2 p0, p1;
                p0.x = __uint_as_float(f2tf32(e0));
                p0.y = __uint_as_float(f2tf32(e1));
                p1.x = __uint_as_float(f2tf32(e2));
                p1.y = __uint_as_float(f2tf32(e3));
                *(float2*)&ps[(im * 16 + g) * PSS + loc] = p0;
                *(float2*)&ps[(im * 16 + 8 + g) * PSS + loc] = p1;
            }
        }
        __syncthreads();

        const float* vc = vs + buf * 64 * VSS;
#pragma unroll
        for (int kf = 0; kf < 8; kf++) {
            const int l0 = kf * 8;
            unsigned b0 = __float_as_uint(vc[(l0 + tg) * VSS + wid * 8 + g]);
            unsigned b1 = __float_as_uint(vc[(l0 + tg + 4) * VSS + wid * 8 + g]);
#pragma unroll
            for (int im = 0; im < 4; im++) {
                int r = im * 16 + g;
                unsigned a0 = __float_as_uint(ps[r * PSS + l0 + tg]);
                unsigned a1 = __float_as_uint(ps[(r + 8) * PSS + l0 + tg]);
                unsigned a2 = __float_as_uint(ps[r * PSS + l0 + tg + 4]);
                unsigned a3 = __float_as_uint(ps[(r + 8) * PSS + l0 + tg + 4]);
                mma_tf32(o[im][0], o[im][1], o[im][2], o[im][3],
                         a0, a1, a2, a3, b0, b1);
            }
        }
        __syncthreads();
    }

#pragma unroll
    for (int im = 0; im < 4; im++) {
#pragma unroll
        for (int hf = 0; hf < 2; hf++) {
            float v = dp[im][hf];
            v += __shfl_xor_sync(0xffffffffu, v, 1);
            v += __shfl_xor_sync(0xffffffffu, v, 2);
            dp[im][hf] = v;
        }
    }
    if (tg == 0) {
#pragma unroll
        for (int im = 0; im < 4; im++) {
            dpart[wid * 64 + im * 16 + g]     = dp[im][0];
            dpart[wid * 64 + im * 16 + 8 + g] = dp[im][1];
        }
    }
    __syncthreads();
    if (tid < 64) {
        float s = 0.f;
#pragma unroll
        for (int w = 0; w < 8; w++) s += dpart[w * 64 + tid];
        denom[tid] = 1.f / s;
    }
    __syncthreads();

#pragma unroll
    for (int im = 0; im < 4; im++) {
        const int r = im * 16 + g;
        const float iv1 = denom[r];
        const float iv2 = denom[r + 8];
        float y0 = o[im][0] * iv1, y1 = o[im][1] * iv1;
        float y2 = o[im][2] * iv2, y3 = o[im][3] * iv2;
        __nv_bfloat16 h0, l0, h1, l1, h2, l2, h3, l3;
        bf16_split(y0, h0, l0); bf16_split(y1, h1, l1);
        bf16_split(y2, h2, l2); bf16_split(y3, h3, l3);
        size_t off1 = (size_t)(bb_ * Tq + t0 + r) * Cq + h * HDq + wid * 8 + 2 * tg;
        size_t off2 = (size_t)(bb_ * Tq + t0 + r + 8) * Cq + h * HDq + wid * 8 + 2 * tg;
        __nv_bfloat162 ph0; ph0.x = h0; ph0.y = h1;
        __nv_bfloat162 pl0; pl0.x = l0; pl0.y = l1;
        __nv_bfloat162 ph1; ph1.x = h2; ph1.y = h3;
        __nv_bfloat162 pl1; pl1.x = l2; pl1.y = l3;
        *(__nv_bfloat162*)&yhi[off1] = ph0;
        *(__nv_bfloat162*)&ylo[off1] = pl0;
        *(__nv_bfloat162*)&yhi[off2] = ph1;
        *(__nv_bfloat162*)&ylo[off2] = pl1;
    }
}

// ---------------------------------------------------------------------------
extern "C" void kernel_launch(void* const* d_in, const int* in_sizes, int n_in,
                              void* d_out, int out_size)
{
    const float* x       = (const float*)d_in[0];
    const float* w1_w    = (const float*)d_in[1];
    const float* w1_b    = (const float*)d_in[2];
    const float* w2      = (const float*)d_in[3];
    const float* b2      = (const float*)d_in[4];
    const float* value_w = (const float*)d_in[5];
    const float* value_b = (const float*)d_in[6];
    const float* proj_w  = (const float*)d_in[7];
    const float* proj_b  = (const float*)d_in[8];
    float* out = (float*)d_out;

    float *pk, *pv, *pw2r;
    __nv_bfloat16 *pahi, *palo, *pw1hi, *pw1lo, *pvwhi, *pvwlo, *ppwhi, *ppwlo;
    cudaGetSymbolAddress((void**)&pk,    g_k);
    cudaGetSymbolAddress((void**)&pv,    g_v);
    cudaGetSymbolAddress((void**)&pw2r,  g_w2r);
    cudaGetSymbolAddress((void**)&pahi,  g_ahi);
    cudaGetSymbolAddress((void**)&palo,  g_alo);
    cudaGetSymbolAddress((void**)&pw1hi, g_w1hi);
    cudaGetSymbolAddress((void**)&pw1lo, g_w1lo);
    cudaGetSymbolAddress((void**)&pvwhi, g_vwhi);
    cudaGetSymbolAddress((void**)&pvwlo, g_vwlo);
    cudaGetSymbolAddress((void**)&ppwhi, g_pwhi);
    cudaGetSymbolAddress((void**)&ppwlo, g_pwlo);

    const int SMEM_GEMM = 8 * PLW * (int)sizeof(unsigned);            // 80 KB
    const int SMEM_ATTN = (64 * KSP2 + 2 * 64 * W2S + 2 * 64 * VSS +
                           64 * PSS + 8 * 64 + 64) * (int)sizeof(float); // ~111 KB
    cudaFuncSetAttribute(gemm_bf16_kernel<true, true>,
                         cudaFuncAttributeMaxDynamicSharedMemorySize, SMEM_GEMM);
    cudaFuncSetAttribute(gemm_bf16_kernel<false, true>,
                         cudaFuncAttributeMaxDynamicSharedMemorySize, SMEM_GEMM);
    cudaFuncSetAttribute(gemm_bf16_kernel<false, false>,
                         cudaFuncAttributeMaxDynamicSharedMemorySize, SMEM_GEMM);
    cudaFuncSetAttribute(attn2_kernel,
                         cudaFuncAttributeMaxDynamicSharedMemorySize, SMEM_ATTN);

    const int Mrows = Bq * Tq;                 // 4096
    dim3 gemm_grid(Cq / 128, Mrows / 128);     // (8, 32)

    // one fused prep pass: x split, 3 weight splits, w2 round
    prep_kernel<<<PREP_TOTAL / 256, 256>>>(
        (const float4*)x, (const float4*)w1_w, (const float4*)value_w,
        (const float4*)proj_w, (const float4*)w2,
        (__nv_bfloat162*)pahi,  (__nv_bfloat162*)palo,
        (__nv_bfloat162*)pw1hi, (__nv_bfloat162*)pw1lo,
        (__nv_bfloat162*)pvwhi, (__nv_bfloat162*)pvwlo,
        (__nv_bfloat162*)ppwhi, (__nv_bfloat162*)ppwlo,
        (float4*)pw2r);

    // k = relu(x @ w1^T + b1), tf32-rounded output
    gemm_bf16_kernel<true, true><<<gemm_grid, 256, SMEM_GEMM>>>(
        pahi, palo, pw1hi, pw1lo, w1_b, pk, Mrows, Cq, Cq);

    // v = x @ value^T + vb, tf32-rounded output
    gemm_bf16_kernel<false, true><<<gemm_grid, 256, SMEM_GEMM>>>(
        pahi, palo, pvwhi, pvwlo, value_b, pv, Mrows, Cq, Cq);

    // attention: writes y bf16 hi/lo planes (overwrites x planes)
    dim3 agrid(Tq / BMq, Hq, Bq);              // (32, 16, 2)
    attn2_kernel<<<agrid, 256, SMEM_ATTN>>>(pk, pv, pw2r, b2, pahi, palo);

    // out = y @ proj^T + pb (fp32 output)
    gemm_bf16_kernel<false, false><<<gemm_grid, 256, SMEM_GEMM>>>(
        pahi, palo, ppwhi, ppwlo, proj_b, out, Mrows, Cq, Cq);
}

// round 15
// speedup vs baseline: 1.0931x; 1.0572x over previous
#include <cuda_runtime.h>
#include <cuda_bf16.h>
#include <math.h>

// Problem constants
#define Bq   2
#define Tq   2048
#define Cq   1024
#define Hq   16
#define HDq  64
#define Mq   2048

// Scratch (allocation-free rule: __device__ globals)
__device__ float         g_k[Bq * Tq * Cq];    // relu(x@w1^T+b1), tf32-rounded
__device__ float         g_v[Bq * Tq * Cq];    // x@value^T+vb, tf32-rounded
__device__ __nv_bfloat16 g_ahi[Bq * Tq * Cq];  // activation hi plane (x, then y)
__device__ __nv_bfloat16 g_alo[Bq * Tq * Cq];  // activation lo plane
__device__ __nv_bfloat16 g_w1hi[Cq * Cq];      // w1 hi plane
__device__ __nv_bfloat16 g_w1lo[Cq * Cq];      // w1 lo plane
__device__ __nv_bfloat16 g_vwhi[Cq * Cq];      // value_w hi plane
__device__ __nv_bfloat16 g_vwlo[Cq * Cq];      // value_w lo plane
__device__ __nv_bfloat16 g_pwhi[Cq * Cq];      // proj_w hi plane
__device__ __nv_bfloat16 g_pwlo[Cq * Cq];      // proj_w lo plane
__device__ float         g_w2r[Hq * HDq * Mq]; // w2 tf32-rounded

// ---------------------------------------------------------------------------
// helpers
// ---------------------------------------------------------------------------
__device__ __forceinline__ unsigned f2tf32(float x) {
    unsigned u;
    asm("cvt.rna.tf32.f32 %0, %1;" : "=r"(u) : "f"(x));
    return u;
}

__device__ __forceinline__ void mma_tf32(
    float& d0, float& d1, float& d2, float& d3,
    unsigned a0, unsigned a1, unsigned a2, unsigned a3,
    unsigned b0, unsigned b1)
{
    asm volatile(
        "mma.sync.aligned.m16n8k8.row.col.f32.tf32.tf32.f32 "
        "{%0,%1,%2,%3}, {%4,%5,%6,%7}, {%8,%9}, {%0,%1,%2,%3};"
        : "+f"(d0), "+f"(d1), "+f"(d2), "+f"(d3)
        : "r"(a0), "r"(a1), "r"(a2), "r"(a3), "r"(b0), "r"(b1));
}

__device__ __forceinline__ void mma_bf16(
    float& d0, float& d1, float& d2, float& d3,
    unsigned a0, unsigned a1, unsigned a2, unsigned a3,
    unsigned b0, unsigned b1)
{
    asm volatile(
        "mma.sync.aligned.m16n8k16.row.col.f32.bf16.bf16.f32 "
        "{%0,%1,%2,%3}, {%4,%5,%6,%7}, {%8,%9}, {%0,%1,%2,%3};"
        : "+f"(d0), "+f"(d1), "+f"(d2), "+f"(d3)
        : "r"(a0), "r"(a1), "r"(a2), "r"(a3), "r"(b0), "r"(b1));
}

__device__ __forceinline__ void cp_async16(void* s, const void* g) {
    unsigned sa = (unsigned)__cvta_generic_to_shared(s);
    asm volatile("cp.async.cg.shared.global [%0], [%1], 16;" :: "r"(sa), "l"(g));
}

__device__ __forceinline__ void bf16_split(float v, __nv_bfloat16& h, __nv_bfloat16& l) {
    h = __float2bfloat16_rn(v);
    l = __float2bfloat16_rn(v - __bfloat162float(h));
}

// ---------------------------------------------------------------------------
// Fused prep kernel (R14, proven): one launch, 5 jobs, range dispatch.
// ---------------------------------------------------------------------------
#define NACT4 ((Bq * Tq * Cq) / 4)
#define NW4   ((Cq * Cq) / 4)
#define NW24  ((Hq * HDq * Mq) / 4)
#define PREP_TOTAL (NACT4 + 3 * NW4 + NW24)

__device__ __forceinline__ void split4_store(
    float4 v, __nv_bfloat162* hi, __nv_bfloat162* lo, int i)
{
    __nv_bfloat16 hx, lx, hy, ly, hz, lz, hw, lw;
    bf16_split(v.x, hx, lx);
    bf16_split(v.y, hy, ly);
    bf16_split(v.z, hz, lz);
    bf16_split(v.w, hw, lw);
    __nv_bfloat162 h0; h0.x = hx; h0.y = hy;
    __nv_bfloat162 h1; h1.x = hz; h1.y = hw;
    __nv_bfloat162 l0; l0.x = lx; l0.y = ly;
    __nv_bfloat162 l1; l1.x = lz; l1.y = lw;
    hi[2 * i] = h0; hi[2 * i + 1] = h1;
    lo[2 * i] = l0; lo[2 * i + 1] = l1;
}

__global__ __launch_bounds__(256) void prep_kernel(
    const float4* __restrict__ x,  const float4* __restrict__ w1,
    const float4* __restrict__ vw, const float4* __restrict__ pw,
    const float4* __restrict__ w2,
    __nv_bfloat162* __restrict__ ahi,  __nv_bfloat162* __restrict__ alo,
    __nv_bfloat162* __restrict__ w1hi, __nv_bfloat162* __restrict__ w1lo,
    __nv_bfloat162* __restrict__ vwhi, __nv_bfloat162* __restrict__ vwlo,
    __nv_bfloat162* __restrict__ pwhi, __nv_bfloat162* __restrict__ pwlo,
    float4* __restrict__ w2r)
{
    int gi = blockIdx.x * 256 + threadIdx.x;
    if (gi < NACT4) {
        split4_store(x[gi], ahi, alo, gi);
    } else if (gi < NACT4 + NW4) {
        int i = gi - NACT4;
        split4_store(w1[i], w1hi, w1lo, i);
    } else if (gi < NACT4 + 2 * NW4) {
        int i = gi - (NACT4 + NW4);
        split4_store(vw[i], vwhi, vwlo, i);
    } else if (gi < NACT4 + 3 * NW4) {
        int i = gi - (NACT4 + 2 * NW4);
        split4_store(pw[i], pwhi, pwlo, i);
    } else {
        int i = gi - (NACT4 + 3 * NW4);
        float4 v = w2[i];
        float4 o;
        o.x = __uint_as_float(f2tf32(v.x));
        o.y = __uint_as_float(f2tf32(v.y));
        o.z = __uint_as_float(f2tf32(v.z));
        o.w = __uint_as_float(f2tf32(v.w));
        w2r[i] = o;
    }
}

// ---------------------------------------------------------------------------
// Dense GEMM via 3x bf16 hi/lo mma (R9, proven): cp.async 2-stage, 2 CTAs/SM
// ---------------------------------------------------------------------------
#define ST   20
#define PLW  2560

template <bool RELU, bool ROUND_OUT>
__global__ __launch_bounds__(256, 2) void gemm_bf16_kernel(
    const __nv_bfloat16* __restrict__ Ahi, const __nv_bfloat16* __restrict__ Alo,
    const __nv_bfloat16* __restrict__ Whi, const __nv_bfloat16* __restrict__ Wlo,
    const float* __restrict__ bias, float* __restrict__ Cmat,
    int Mdim, int Ndim, int Kdim)
{
    extern __shared__ unsigned smu[];
    unsigned* sAh = smu;
    unsigned* sAl = sAh + 2 * PLW;
    unsigned* sBh = sAl + 2 * PLW;
    unsigned* sBl = sBh + 2 * PLW;

    const int tid  = threadIdx.x;
    const int lane = tid & 31;
    const int wid  = tid >> 5;
    const int wm   = (wid & 3) * 32;
    const int wn   = (wid >> 2) * 64;
    const int g    = lane >> 2;
    const int tg   = lane & 3;

    const int m0 = blockIdx.y * 128;
    const int n0 = blockIdx.x * 128;
    const int NK = Kdim >> 5;

    float acc[2][8][4];
#pragma unroll
    for (int im = 0; im < 2; im++)
#pragma unroll
        for (int in = 0; in < 8; in++)
#pragma unroll
            for (int e = 0; e < 4; e++) acc[im][in][e] = 0.f;

    auto load_stage = [&](int kt, int st) {
        const int k0 = kt << 5;
#pragma unroll
        for (int i = 0; i < 8; i++) {
            int cc = tid + (i & 1) * 256;
            int r  = cc >> 2;
            int j  = cc & 3;
            if ((i >> 1) == 0)
                cp_async16(&sAh[st * PLW + r * ST + 4 * j],
                           &Ahi[(size_t)(m0 + r) * Kdim + k0 + 8 * j]);
            else if ((i >> 1) == 1)
                cp_async16(&sAl[st * PLW + r * ST + 4 * j],
                           &Alo[(size_t)(m0 + r) * Kdim + k0 + 8 * j]);
            else if ((i >> 1) == 2)
                cp_async16(&sBh[st * PLW + r * ST + 4 * j],
                           &Whi[(size_t)(n0 + r) * Kdim + k0 + 8 * j]);
            else
                cp_async16(&sBl[st * PLW + r * ST + 4 * j],
                           &Wlo[(size_t)(n0 + r) * Kdim + k0 + 8 * j]);
        }
        asm volatile("cp.async.commit_group;" ::: "memory");
    };

    load_stage(0, 0);

    for (int kt = 0; kt < NK; kt++) {
        const int cur = kt & 1;
        if (kt + 1 < NK) {
            load_stage(kt + 1, (kt + 1) & 1);
            asm volatile("cp.async.wait_group 1;" ::: "memory");
        } else {
            asm volatile("cp.async.wait_group 0;" ::: "memory");
        }
        __syncthreads();

        const unsigned* pAh = sAh + cur * PLW;
        const unsigned* pAl = sAl + cur * PLW;
        const unsigned* pBh = sBh + cur * PLW;
        const unsigned* pBl = sBl + cur * PLW;

#pragma unroll
        for (int kw = 0; kw < 16; kw += 8) {
            unsigned ah[2][4], al[2][4];
#pragma unroll
            for (int im = 0; im < 2; im++) {
                int r = wm + im * 16 + g;
                ah[im][0] = pAh[r * ST + kw + tg];
                ah[im][1] = pAh[(r + 8) * ST + kw + tg];
                ah[im][2] = pAh[r * ST + kw + tg + 4];
                ah[im][3] = pAh[(r + 8) * ST + kw + tg + 4];
                al[im][0] = pAl[r * ST + kw + tg];
                al[im][1] = pAl[(r + 8) * ST + kw + tg];
                al[im][2] = pAl[r * ST + kw + tg + 4];
                al[im][3] = pAl[(r + 8) * ST + kw + tg + 4];
            }
#pragma unroll
            for (int in = 0; in < 8; in++) {
                int c = wn + in * 8 + g;
                unsigned bh0 = pBh[c * ST + kw + tg];
                unsigned bh1 = pBh[c * ST + kw + tg + 4];
                unsigned bl0 = pBl[c * ST + kw + tg];
                unsigned bl1 = pBl[c * ST + kw + tg + 4];
#pragma unroll
                for (int im = 0; im < 2; im++) {
                    float* d = acc[im][in];
                    mma_bf16(d[0], d[1], d[2], d[3],
                             ah[im][0], ah[im][1], ah[im][2], ah[im][3],
                             bh0, bh1);
                    mma_bf16(d[0], d[1], d[2], d[3],
                             ah[im][0], ah[im][1], ah[im][2], ah[im][3],
                             bl0, bl1);
                    mma_bf16(d[0], d[1], d[2], d[3],
                             al[im][0], al[im][1], al[im][2], al[im][3],
                             bh0, bh1);
                }
            }
        }
        __syncthreads();
    }

#pragma unroll
    for (int in = 0; in < 8; in++) {
        int col = n0 + wn + in * 8 + 2 * tg;
        float2 bz = *(const float2*)&bias[col];
#pragma unroll
        for (int im = 0; im < 2; im++) {
            int row = m0 + wm + im * 16 + g;
            float v0 = acc[im][in][0] + bz.x;
            float v1 = acc[im][in][1] + bz.y;
            float v2 = acc[im][in][2] + bz.x;
            float v3 = acc[im][in][3] + bz.y;
            if (RELU) {
                v0 = fmaxf(v0, 0.f); v1 = fmaxf(v1, 0.f);
                v2 = fmaxf(v2, 0.f); v3 = fmaxf(v3, 0.f);
            }
            if (ROUND_OUT) {
                v0 = __uint_as_float(f2tf32(v0));
                v1 = __uint_as_float(f2tf32(v1));
                v2 = __uint_as_float(f2tf32(v2));
                v3 = __uint_as_float(f2tf32(v3));
            }
            float2 p0; p0.x = v0; p0.y = v1;
            float2 p1; p1.x = v2; p1.y = v3;
            *(float2*)&Cmat[(size_t)row * Ndim + col] = p0;
            *(float2*)&Cmat[(size_t)(row + 8) * Ndim + col] = p1;
        }
    }
}

// ---------------------------------------------------------------------------
// Chunked fused attention, re-tiled warps: warp = (row-half im2, col-quarter
// in2) -> 32 rows x 16 cols per warp in both score and PV. Fragment LDS per
// warp-chunk drops 288 -> 192 at identical mma count and math.
// ---------------------------------------------------------------------------
#define BMq  64
#define KSP2 68
#define W2S  72
#define VSS  72
#define PSS  68

__global__ __launch_bounds__(256, 2) void attn2_kernel(
    const float* __restrict__ gk, const float* __restrict__ gv,
    const float* __restrict__ w2r, const float* __restrict__ b2,
    __nv_bfloat16* __restrict__ yhi, __nv_bfloat16* __restrict__ ylo)
{
    extern __shared__ float sm[];
    float* ks    = sm;
    float* w2s   = ks + 64 * KSP2;
    float* vs    = w2s + 2 * 64 * W2S;
    float* ps    = vs + 2 * 64 * VSS;
    float* dpart = ps + 64 * PSS;
    float* denom = dpart + 8 * 64;

    const int t0  = blockIdx.x * BMq;
    const int h   = blockIdx.y;
    const int bb_ = blockIdx.z;
    const int tid = threadIdx.x;
    const int lane = tid & 31;
    const int wid  = tid >> 5;
    const int g    = lane >> 2;
    const int tg   = lane & 3;
    const int im2  = wid >> 2;         // 0..1: row half (m-tiles 2*im2, 2*im2+1)
    const int in2  = wid & 3;          // 0..3: col quarter (16 cols)

    const int nch = (t0 >> 6) + 1;

    auto stage = [&](int c, int buf) {
        const int c0 = c << 6;
        float* w2d = w2s + buf * 64 * W2S;
        float* vsd = vs + buf * 64 * VSS;
        const float* w2g = w2r + (size_t)h * HDq * Mq + c0;
        const float* vg  = gv + (size_t)bb_ * Tq * Cq + (size_t)c0 * Cq + h * HDq;
#pragma unroll
        for (int i = 0; i < 4; i++) {
            int cc = tid + i * 256;
            int d  = cc >> 4;
            int m4 = (cc & 15) << 2;
            cp_async16(&w2d[d * W2S + m4], &w2g[(size_t)d * Mq + m4]);
        }
#pragma unroll
        for (int i = 0; i < 4; i++) {
            int cc = tid + i * 256;
            int l  = cc >> 4;
            int d4 = (cc & 15) << 2;
            cp_async16(&vsd[l * VSS + d4], &vg[(size_t)l * Cq + d4]);
        }
        asm volatile("cp.async.commit_group;" ::: "memory");
    };

    {
#pragma unroll
        for (int i = 0; i < 4; i++) {
            int cc = tid + i * 256;
            int r  = cc >> 4;
            int d4 = (cc & 15) << 2;
            cp_async16(&ks[r * KSP2 + d4],
                       &gk[(size_t)(bb_ * Tq + t0 + r) * Cq + h * HDq + d4]);
        }
        stage(0, 0);
    }

    float o[2][2][4];    // PV acc: [i2 row-tile][in col-block][4]
    float dp[2][2];      // denom partials: [i2][row-half-of-tile]
#pragma unroll
    for (int i2 = 0; i2 < 2; i2++) {
#pragma unroll
        for (int in = 0; in < 2; in++)
#pragma unroll
            for (int e = 0; e < 4; e++) o[i2][in][e] = 0.f;
        dp[i2][0] = 0.f; dp[i2][1] = 0.f;
    }

    for (int c = 0; c < nch; c++) {
        const int buf = c & 1;
        if (c + 1 < nch) {
            stage(c + 1, (c + 1) & 1);
            asm volatile("cp.async.wait_group 1;" ::: "memory");
        } else {
            asm volatile("cp.async.wait_group 0;" ::: "memory");
        }
        __syncthreads();

        // ---- score mma: warp covers rows [32*im2,+32) x cols [16*in2,+16) ----
        const float* w2c = w2s + buf * 64 * W2S;
        float d[2][2][4];
#pragma unroll
        for (int i2 = 0; i2 < 2; i2++)
#pragma unroll
            for (int in = 0; in < 2; in++)
#pragma unroll
                for (int e = 0; e < 4; e++) d[i2][in][e] = 0.f;

#pragma unroll
        for (int kf = 0; kf < 8; kf++) {
            unsigned a0[2], a1[2], a2[2], a3[2];
#pragma unroll
            for (int i2 = 0; i2 < 2; i2++) {
                int r = (im2 * 2 + i2) * 16 + g;
                a0[i2] = __float_as_uint(ks[r * KSP2 + kf * 8 + tg]);
                a1[i2] = __float_as_uint(ks[(r + 8) * KSP2 + kf * 8 + tg]);
                a2[i2] = __float_as_uint(ks[r * KSP2 + kf * 8 + tg + 4]);
                a3[i2] = __float_as_uint(ks[(r + 8) * KSP2 + kf * 8 + tg + 4]);
            }
#pragma unroll
            for (int in = 0; in < 2; in++) {
                int cc = in2 * 16 + in * 8 + g;
                unsigned b0 = __float_as_uint(w2c[(kf * 8 + tg) * W2S + cc]);
                unsigned b1 = __float_as_uint(w2c[(kf * 8 + tg + 4) * W2S + cc]);
#pragma unroll
                for (int i2 = 0; i2 < 2; i2++)
                    mma_tf32(d[i2][in][0], d[i2][in][1], d[i2][in][2], d[i2][in][3],
                             a0[i2], a1[i2], a2[i2], a3[i2], b0, b1);
            }
        }

        // ---- bias + exp + causal mask + ps store + denom partials ----
#pragma unroll
        for (int in = 0; in < 2; in++) {
            const int colb = (c << 6) + in2 * 16 + in * 8 + 2 * tg;
            float2 bz = *(const float2*)&b2[colb];
            const int loc = in2 * 16 + in * 8 + 2 * tg;
#pragma unroll
            for (int i2 = 0; i2 < 2; i2++) {
                const int imt = im2 * 2 + i2;
                const int r1 = t0 + imt * 16 + g;
                const int r2 = r1 + 8;
                float s0 = d[i2][in][0] + bz.x;
                float s1 = d[i2][in][1] + bz.y;
                float s2 = d[i2][in][2] + bz.x;
                float s3 = d[i2][in][3] + bz.y;
                float e0 = (colb     <= r1) ? __expf(s0) : 0.f;
                float e1 = (colb + 1 <= r1) ? __expf(s1) : 0.f;
                float e2 = (colb     <= r2) ? __expf(s2) : 0.f;
                float e3 = (colb + 1 <= r2) ? __expf(s3) : 0.f;
                dp[i2][0] += e0 + e1;
                dp[i2][1] += e2 + e3;
                float2 p0, p1;
                p0.x = __uint_as_float(f2tf32(e0));
                p0.y = __uint_as_float(f2tf32(e1));
                p1.x = __uint_as_float(f2tf32(e2));
                p1.y = __uint_as_float(f2tf32(e3));
                *(float2*)&ps[(imt * 16 + g) * PSS + loc] = p0;
                *(float2*)&ps[(imt * 16 + 8 + g) * PSS + loc] = p1;
            }
        }
        __syncthreads();

        // ---- PV mma: warp covers rows [32*im2,+32) x hd cols [16*in2,+16) ----
        const float* vc = vs + buf * 64 * VSS;
#pragma unroll
        for (int kf = 0; kf < 8; kf++) {
            const int l0 = kf * 8;
            unsigned a0[2], a1[2], a2[2], a3[2];
#pragma unroll
            for (int i2 = 0; i2 < 2; i2++) {
                int r = (im2 * 2 + i2) * 16 + g;
                a0[i2] = __float_as_uint(ps[r * PSS + l0 + tg]);
                a1[i2] = __float_as_uint(ps[(r + 8) * PSS + l0 + tg]);
                a2[i2] = __float_as_uint(ps[r * PSS + l0 + tg + 4]);
                a3[i2] = __float_as_uint(ps[(r + 8) * PSS + l0 + tg + 4]);
            }
#pragma unroll
            for (int in = 0; in < 2; in++) {
                int hd = in2 * 16 + in * 8 + g;
                unsigned b0 = __float_as_uint(vc[(l0 + tg) * VSS + hd]);
                unsigned b1 = __float_as_uint(vc[(l0 + tg + 4) * VSS + hd]);
#pragma unroll
                for (int i2 = 0; i2 < 2; i2++)
                    mma_tf32(o[i2][in][0], o[i2][in][1], o[i2][in][2], o[i2][in][3],
                             a0[i2], a1[i2], a2[i2], a3[i2], b0, b1);
            }
        }
        __syncthreads();
    }

    // ---- denominator reduction: quad shuffle, then cross-warp sum ----
#pragma unroll
    for (int i2 = 0; i2 < 2; i2++) {
#pragma unroll
        for (int hf = 0; hf < 2; hf++) {
            float v = dp[i2][hf];
            v += __shfl_xor_sync(0xffffffffu, v, 1);
            v += __shfl_xor_sync(0xffffffffu, v, 2);
            dp[i2][hf] = v;
        }
    }
    if (tg == 0) {
#pragma unroll
        for (int t = 0; t < 4; t++) {
            float v0 = 0.f, v1 = 0.f;
            if ((t >> 1) == im2) {
                v0 = dp[t & 1][0];
                v1 = dp[t & 1][1];
            }
            dpart[wid * 64 + t * 16 + g]     = v0;
            dpart[wid * 64 + t * 16 + 8 + g] = v1;
        }
    }
    __syncthreads();
    if (tid < 64) {
        float s = 0.f;
#pragma unroll
        for (int w = 0; w < 8; w++) s += dpart[w * 64 + tid];
        denom[tid] = 1.f / s;
    }
    __syncthreads();

    // ---- output: y as bf16 hi/lo planes ----
#pragma unroll
    for (int i2 = 0; i2 < 2; i2++) {
        const int imt = im2 * 2 + i2;
        const int r = imt * 16 + g;
        const float iv1 = denom[r];
        const float iv2 = denom[r + 8];
#pragma unroll
        for (int in = 0; in < 2; in++) {
            float y0 = o[i2][in][0] * iv1, y1 = o[i2][in][1] * iv1;
            float y2 = o[i2][in][2] * iv2, y3 = o[i2][in][3] * iv2;
            __nv_bfloat16 h0, l0, h1, l1, h2, l2, h3, l3;
            bf16_split(y0, h0, l0); bf16_split(y1, h1, l1);
            bf16_split(y2, h2, l2); bf16_split(y3, h3, l3);
            const int cb = h * HDq + in2 * 16 + in * 8 + 2 * tg;
            size_t off1 = (size_t)(bb_ * Tq + t0 + r) * Cq + cb;
            size_t off2 = (size_t)(bb_ * Tq + t0 + r + 8) * Cq + cb;
            __nv_bfloat162 ph0; ph0.x = h0; ph0.y = h1;
            __nv_bfloat162 pl0; pl0.x = l0; pl0.y = l1;
            __nv_bfloat162 ph1; ph1.x = h2; ph1.y = h3;
            __nv_bfloat162 pl1; pl1.x = l2; pl1.y = l3;
            *(__nv_bfloat162*)&yhi[off1] = ph0;
            *(__nv_bfloat162*)&ylo[off1] = pl0;
            *(__nv_bfloat162*)&yhi[off2] = ph1;
            *(__nv_bfloat162*)&ylo[off2] = pl1;
        }
    }
}

// ---------------------------------------------------------------------------
extern "C" void kernel_launch(void* const* d_in, const int* in_sizes, int n_in,
                              void* d_out, int out_size)
{
    const float* x       = (const float*)d_in[0];
    const float* w1_w    = (const float*)d_in[1];
    const float* w1_b    = (const float*)d_in[2];
    const float* w2      = (const float*)d_in[3];
    const float* b2      = (const float*)d_in[4];
    const float* value_w = (const float*)d_in[5];
    const float* value_b = (const float*)d_in[6];
    const float* proj_w  = (const float*)d_in[7];
    const float* proj_b  = (const float*)d_in[8];
    float* out = (float*)d_out;

    float *pk, *pv, *pw2r;
    __nv_bfloat16 *pahi, *palo, *pw1hi, *pw1lo, *pvwhi, *pvwlo, *ppwhi, *ppwlo;
    cudaGetSymbolAddress((void**)&pk,    g_k);
    cudaGetSymbolAddress((void**)&pv,    g_v);
    cudaGetSymbolAddress((void**)&pw2r,  g_w2r);
    cudaGetSymbolAddress((void**)&pahi,  g_ahi);
    cudaGetSymbolAddress((void**)&palo,  g_alo);
    cudaGetSymbolAddress((void**)&pw1hi, g_w1hi);
    cudaGetSymbolAddress((void**)&pw1lo, g_w1lo);
    cudaGetSymbolAddress((void**)&pvwhi, g_vwhi);
    cudaGetSymbolAddress((void**)&pvwlo, g_vwlo);
    cudaGetSymbolAddress((void**)&ppwhi, g_pwhi);
    cudaGetSymbolAddress((void**)&ppwlo, g_pwlo);

    const int SMEM_GEMM = 8 * PLW * (int)sizeof(unsigned);            // 80 KB
    const int SMEM_ATTN = (64 * KSP2 + 2 * 64 * W2S + 2 * 64 * VSS +
                           64 * PSS + 8 * 64 + 64) * (int)sizeof(float);
    cudaFuncSetAttribute(gemm_bf16_kernel<true, true>,
                         cudaFuncAttributeMaxDynamicSharedMemorySize, SMEM_GEMM);
    cudaFuncSetAttribute(gemm_bf16_kernel<false, true>,
                         cudaFuncAttributeMaxDynamicSharedMemorySize, SMEM_GEMM);
    cudaFuncSetAttribute(gemm_bf16_kernel<false, false>,
                         cudaFuncAttributeMaxDynamicSharedMemorySize, SMEM_GEMM);
    cudaFuncSetAttribute(attn2_kernel,
                         cudaFuncAttributeMaxDynamicSharedMemorySize, SMEM_ATTN);

    const int Mrows = Bq * Tq;                 // 4096
    dim3 gemm_grid(Cq / 128, Mrows / 128);     // (8, 32)

    // one fused prep pass: x split, 3 weight splits, w2 round
    prep_kernel<<<PREP_TOTAL / 256, 256>>>(
        (const float4*)x, (const float4*)w1_w, (const float4*)value_w,
        (const float4*)proj_w, (const float4*)w2,
        (__nv_bfloat162*)pahi,  (__nv_bfloat162*)palo,
        (__nv_bfloat162*)pw1hi, (__nv_bfloat162*)pw1lo,
        (__nv_bfloat162*)pvwhi, (__nv_bfloat162*)pvwlo,
        (__nv_bfloat162*)ppwhi, (__nv_bfloat162*)ppwlo,
        (float4*)pw2r);

    // k = relu(x @ w1^T + b1), tf32-rounded output
    gemm_bf16_kernel<true, true><<<gemm_grid, 256, SMEM_GEMM>>>(
        pahi, palo, pw1hi, pw1lo, w1_b, pk, Mrows, Cq, Cq);

    // v = x @ value^T + vb, tf32-rounded output
    gemm_bf16_kernel<false, true><<<gemm_grid, 256, SMEM_GEMM>>>(
        pahi, palo, pvwhi, pvwlo, value_b, pv, Mrows, Cq, Cq);

    // attention: writes y bf16 hi/lo planes (overwrites x planes)
    dim3 agrid(Tq / BMq, Hq, Bq);              // (32, 16, 2)
    attn2_kernel<<<agrid, 256, SMEM_ATTN>>>(pk, pv, pw2r, b2, pahi, palo);

    // out = y @ proj^T + pb (fp32 output)
    gemm_bf16_kernel<false, false><<<gemm_grid, 256, SMEM_GEMM>>>(
        pahi, palo, ppwhi, ppwlo, proj_b, out, Mrows, Cq, Cq);
}

// round 16
// speedup vs baseline: 1.1812x; 1.0806x over previous
#include <cuda_runtime.h>
#include <cuda_bf16.h>
#include <math.h>

// Problem constants
#define Bq   2
#define Tq   2048
#define Cq   1024
#define Hq   16
#define HDq  64
#define Mq   2048

// Scratch (allocation-free rule: __device__ globals)
__device__ __nv_bfloat16 g_kb[Bq * Tq * Cq];   // relu(x@w1^T+b1), bf16
__device__ float         g_v[Bq * Tq * Cq];    // x@value^T+vb, tf32-rounded
__device__ __nv_bfloat16 g_ahi[Bq * Tq * Cq];  // activation hi plane (x, then y)
__device__ __nv_bfloat16 g_alo[Bq * Tq * Cq];  // activation lo plane
__device__ __nv_bfloat16 g_w1hi[Cq * Cq];      // w1 hi plane
__device__ __nv_bfloat16 g_w1lo[Cq * Cq];      // w1 lo plane
__device__ __nv_bfloat16 g_vwhi[Cq * Cq];      // value_w hi plane
__device__ __nv_bfloat16 g_vwlo[Cq * Cq];      // value_w lo plane
__device__ __nv_bfloat16 g_pwhi[Cq * Cq];      // proj_w hi plane
__device__ __nv_bfloat16 g_pwlo[Cq * Cq];      // proj_w lo plane
__device__ __nv_bfloat16 g_w2b[Hq * Mq * HDq]; // w2 transposed bf16: [h][m][d]

// ---------------------------------------------------------------------------
// helpers
// ---------------------------------------------------------------------------
__device__ __forceinline__ unsigned f2tf32(float x) {
    unsigned u;
    asm("cvt.rna.tf32.f32 %0, %1;" : "=r"(u) : "f"(x));
    return u;
}

__device__ __forceinline__ void mma_tf32(
    float& d0, float& d1, float& d2, float& d3,
    unsigned a0, unsigned a1, unsigned a2, unsigned a3,
    unsigned b0, unsigned b1)
{
    asm volatile(
        "mma.sync.aligned.m16n8k8.row.col.f32.tf32.tf32.f32 "
        "{%0,%1,%2,%3}, {%4,%5,%6,%7}, {%8,%9}, {%0,%1,%2,%3};"
        : "+f"(d0), "+f"(d1), "+f"(d2), "+f"(d3)
        : "r"(a0), "r"(a1), "r"(a2), "r"(a3), "r"(b0), "r"(b1));
}

__device__ __forceinline__ void mma_bf16(
    float& d0, float& d1, float& d2, float& d3,
    unsigned a0, unsigned a1, unsigned a2, unsigned a3,
    unsigned b0, unsigned b1)
{
    asm volatile(
        "mma.sync.aligned.m16n8k16.row.col.f32.bf16.bf16.f32 "
        "{%0,%1,%2,%3}, {%4,%5,%6,%7}, {%8,%9}, {%0,%1,%2,%3};"
        : "+f"(d0), "+f"(d1), "+f"(d2), "+f"(d3)
        : "r"(a0), "r"(a1), "r"(a2), "r"(a3), "r"(b0), "r"(b1));
}

__device__ __forceinline__ void cp_async16(void* s, const void* g) {
    unsigned sa = (unsigned)__cvta_generic_to_shared(s);
    asm volatile("cp.async.cg.shared.global [%0], [%1], 16;" :: "r"(sa), "l"(g));
}

__device__ __forceinline__ void bf16_split(float v, __nv_bfloat16& h, __nv_bfloat16& l) {
    h = __float2bfloat16_rn(v);
    l = __float2bfloat16_rn(v - __bfloat162float(h));
}

// ---------------------------------------------------------------------------
// Fused prep kernel: x + 3 weight splits (w2 handled by transpose kernel)
// ---------------------------------------------------------------------------
#define NACT4 ((Bq * Tq * Cq) / 4)
#define NW4   ((Cq * Cq) / 4)
#define PREP_TOTAL (NACT4 + 3 * NW4)

__device__ __forceinline__ void split4_store(
    float4 v, __nv_bfloat162* hi, __nv_bfloat162* lo, int i)
{
    __nv_bfloat16 hx, lx, hy, ly, hz, lz, hw, lw;
    bf16_split(v.x, hx, lx);
    bf16_split(v.y, hy, ly);
    bf16_split(v.z, hz, lz);
    bf16_split(v.w, hw, lw);
    __nv_bfloat162 h0; h0.x = hx; h0.y = hy;
    __nv_bfloat162 h1; h1.x = hz; h1.y = hw;
    __nv_bfloat162 l0; l0.x = lx; l0.y = ly;
    __nv_bfloat162 l1; l1.x = lz; l1.y = lw;
    hi[2 * i] = h0; hi[2 * i + 1] = h1;
    lo[2 * i] = l0; lo[2 * i + 1] = l1;
}

__global__ __launch_bounds__(256) void prep_kernel(
    const float4* __restrict__ x,  const float4* __restrict__ w1,
    const float4* __restrict__ vw, const float4* __restrict__ pw,
    __nv_bfloat162* __restrict__ ahi,  __nv_bfloat162* __restrict__ alo,
    __nv_bfloat162* __restrict__ w1hi, __nv_bfloat162* __restrict__ w1lo,
    __nv_bfloat162* __restrict__ vwhi, __nv_bfloat162* __restrict__ vwlo,
    __nv_bfloat162* __restrict__ pwhi, __nv_bfloat162* __restrict__ pwlo)
{
    int gi = blockIdx.x * 256 + threadIdx.x;
    if (gi < NACT4) {
        split4_store(x[gi], ahi, alo, gi);
    } else if (gi < NACT4 + NW4) {
        int i = gi - NACT4;
        split4_store(w1[i], w1hi, w1lo, i);
    } else if (gi < NACT4 + 2 * NW4) {
        int i = gi - (NACT4 + NW4);
        split4_store(vw[i], vwhi, vwlo, i);
    } else {
        int i = gi - (NACT4 + 2 * NW4);
        split4_store(pw[i], pwhi, pwlo, i);
    }
}

// w2 transpose + bf16: [h][d][m] fp32 -> [h][m][d] bf16 via 64x64 smem tiles
__global__ __launch_bounds__(256) void w2t_kernel(
    const float* __restrict__ w2, __nv_bfloat16* __restrict__ w2b)
{
    __shared__ float t[64][65];
    const int h  = blockIdx.y;
    const int m0 = blockIdx.x * 64;
    const int tid = threadIdx.x;
#pragma unroll
    for (int i = 0; i < 16; i++) {
        int idx = tid + i * 256;
        int d = idx >> 6, m = idx & 63;
        t[d][m] = w2[(size_t)h * HDq * Mq + (size_t)d * Mq + m0 + m];
    }
    __syncthreads();
#pragma unroll
    for (int i = 0; i < 16; i++) {
        int idx = tid + i * 256;
        int m = idx >> 6, d = idx & 63;
        w2b[(size_t)h * Mq * HDq + (size_t)(m0 + m) * HDq + d] =
            __float2bfloat16_rn(t[d][m]);
    }
}

// ---------------------------------------------------------------------------
// Dense GEMM via 3x bf16 hi/lo mma (R9, proven): cp.async 2-stage, 2 CTAs/SM
// OMODE: 0 = fp32 out, 1 = tf32-rounded fp32 out, 2 = bf16 out
// ---------------------------------------------------------------------------
#define ST   20
#define PLW  2560

template <bool RELU, int OMODE>
__global__ __launch_bounds__(256, 2) void gemm_bf16_kernel(
    const __nv_bfloat16* __restrict__ Ahi, const __nv_bfloat16* __restrict__ Alo,
    const __nv_bfloat16* __restrict__ Whi, const __nv_bfloat16* __restrict__ Wlo,
    const float* __restrict__ bias, void* __restrict__ Cout,
    int Mdim, int Ndim, int Kdim)
{
    extern __shared__ unsigned smu[];
    unsigned* sAh = smu;
    unsigned* sAl = sAh + 2 * PLW;
    unsigned* sBh = sAl + 2 * PLW;
    unsigned* sBl = sBh + 2 * PLW;

    const int tid  = threadIdx.x;
    const int lane = tid & 31;
    const int wid  = tid >> 5;
    const int wm   = (wid & 3) * 32;
    const int wn   = (wid >> 2) * 64;
    const int g    = lane >> 2;
    const int tg   = lane & 3;

    const int m0 = blockIdx.y * 128;
    const int n0 = blockIdx.x * 128;
    const int NK = Kdim >> 5;

    float acc[2][8][4];
#pragma unroll
    for (int im = 0; im < 2; im++)
#pragma unroll
        for (int in = 0; in < 8; in++)
#pragma unroll
            for (int e = 0; e < 4; e++) acc[im][in][e] = 0.f;

    auto load_stage = [&](int kt, int st) {
        const int k0 = kt << 5;
#pragma unroll
        for (int i = 0; i < 8; i++) {
            int cc = tid + (i & 1) * 256;
            int r  = cc >> 2;
            int j  = cc & 3;
            if ((i >> 1) == 0)
                cp_async16(&sAh[st * PLW + r * ST + 4 * j],
                           &Ahi[(size_t)(m0 + r) * Kdim + k0 + 8 * j]);
            else if ((i >> 1) == 1)
                cp_async16(&sAl[st * PLW + r * ST + 4 * j],
                           &Alo[(size_t)(m0 + r) * Kdim + k0 + 8 * j]);
            else if ((i >> 1) == 2)
                cp_async16(&sBh[st * PLW + r * ST + 4 * j],
                           &Whi[(size_t)(n0 + r) * Kdim + k0 + 8 * j]);
            else
                cp_async16(&sBl[st * PLW + r * ST + 4 * j],
                           &Wlo[(size_t)(n0 + r) * Kdim + k0 + 8 * j]);
        }
        asm volatile("cp.async.commit_group;" ::: "memory");
    };

    load_stage(0, 0);

    for (int kt = 0; kt < NK; kt++) {
        const int cur = kt & 1;
        if (kt + 1 < NK) {
            load_stage(kt + 1, (kt + 1) & 1);
            asm volatile("cp.async.wait_group 1;" ::: "memory");
        } else {
            asm volatile("cp.async.wait_group 0;" ::: "memory");
        }
        __syncthreads();

        const unsigned* pAh = sAh + cur * PLW;
        const unsigned* pAl = sAl + cur * PLW;
        const unsigned* pBh = sBh + cur * PLW;
        const unsigned* pBl = sBl + cur * PLW;

#pragma unroll
        for (int kw = 0; kw < 16; kw += 8) {
            unsigned ah[2][4], al[2][4];
#pragma unroll
            for (int im = 0; im < 2; im++) {
                int r = wm + im * 16 + g;
                ah[im][0] = pAh[r * ST + kw + tg];
                ah[im][1] = pAh[(r + 8) * ST + kw + tg];
                ah[im][2] = pAh[r * ST + kw + tg + 4];
                ah[im][3] = pAh[(r + 8) * ST + kw + tg + 4];
                al[im][0] = pAl[r * ST + kw + tg];
                al[im][1] = pAl[(r + 8) * ST + kw + tg];
                al[im][2] = pAl[r * ST + kw + tg + 4];
                al[im][3] = pAl[(r + 8) * ST + kw + tg + 4];
            }
#pragma unroll
            for (int in = 0; in < 8; in++) {
                int c = wn + in * 8 + g;
                unsigned bh0 = pBh[c * ST + kw + tg];
                unsigned bh1 = pBh[c * ST + kw + tg + 4];
                unsigned bl0 = pBl[c * ST + kw + tg];
                unsigned bl1 = pBl[c * ST + kw + tg + 4];
#pragma unroll
                for (int im = 0; im < 2; im++) {
                    float* d = acc[im][in];
                    mma_bf16(d[0], d[1], d[2], d[3],
                             ah[im][0], ah[im][1], ah[im][2], ah[im][3],
                             bh0, bh1);
                    mma_bf16(d[0], d[1], d[2], d[3],
                             ah[im][0], ah[im][1], ah[im][2], ah[im][3],
                             bl0, bl1);
                    mma_bf16(d[0], d[1], d[2], d[3],
                             al[im][0], al[im][1], al[im][2], al[im][3],
                             bh0, bh1);
                }
            }
        }
        __syncthreads();
    }

#pragma unroll
    for (int in = 0; in < 8; in++) {
        int col = n0 + wn + in * 8 + 2 * tg;
        float2 bz = *(const float2*)&bias[col];
#pragma unroll
        for (int im = 0; im < 2; im++) {
            int row = m0 + wm + im * 16 + g;
            float v0 = acc[im][in][0] + bz.x;
            float v1 = acc[im][in][1] + bz.y;
            float v2 = acc[im][in][2] + bz.x;
            float v3 = acc[im][in][3] + bz.y;
            if (RELU) {
                v0 = fmaxf(v0, 0.f); v1 = fmaxf(v1, 0.f);
                v2 = fmaxf(v2, 0.f); v3 = fmaxf(v3, 0.f);
            }
            if (OMODE == 2) {
                __nv_bfloat16* Cb = (__nv_bfloat16*)Cout;
                __nv_bfloat162 p0, p1;
                p0.x = __float2bfloat16_rn(v0); p0.y = __float2bfloat16_rn(v1);
                p1.x = __float2bfloat16_rn(v2); p1.y = __float2bfloat16_rn(v3);
                *(__nv_bfloat162*)&Cb[(size_t)row * Ndim + col] = p0;
                *(__nv_bfloat162*)&Cb[(size_t)(row + 8) * Ndim + col] = p1;
            } else {
                float* Cf = (float*)Cout;
                if (OMODE == 1) {
                    v0 = __uint_as_float(f2tf32(v0));
                    v1 = __uint_as_float(f2tf32(v1));
                    v2 = __uint_as_float(f2tf32(v2));
                    v3 = __uint_as_float(f2tf32(v3));
                }
                float2 p0; p0.x = v0; p0.y = v1;
                float2 p1; p1.x = v2; p1.y = v3;
                *(float2*)&Cf[(size_t)row * Ndim + col] = p0;
                *(float2*)&Cf[(size_t)(row + 8) * Ndim + col] = p1;
            }
        }
    }
}

// ---------------------------------------------------------------------------
// Chunked fused attention: score phase in single bf16 (K bf16, w2 bf16
// pre-transposed [m][d]), PV in tf32 (unchanged). Warp tile 32x16.
// smem (32-bit word offsets):
//   ks   [0, 2304)        64 rows x 36 words (64 bf16 + pad)
//   w2s  [2304, 6912)     2 bufs x 64 m-rows x 36 words (64 bf16 + pad)
//   vs   [6912, 16128)    2 bufs x 64 rows x 72 floats
//   ps   [16128, 20480)   64 rows x 68 floats
//   dpart[20480, 20992)   8 x 64
//   denom[20992, 21056)
// ---------------------------------------------------------------------------
#define BMq   64
#define KSB   36
#define W2B   36
#define VSS   72
#define PSS   68
#define ATTN_WORDS 21056

__global__ __launch_bounds__(256, 2) void attn2_kernel(
    const __nv_bfloat16* __restrict__ gk, const float* __restrict__ gv,
    const __nv_bfloat16* __restrict__ w2b, const float* __restrict__ b2,
    __nv_bfloat16* __restrict__ yhi, __nv_bfloat16* __restrict__ ylo)
{
    extern __shared__ float sm[];
    unsigned* ksu  = (unsigned*)sm;            // bf16 pairs
    unsigned* w2su = (unsigned*)sm + 2304;     // bf16 pairs
    float* vs    = sm + 6912;
    float* ps    = sm + 16128;
    float* dpart = sm + 20480;
    float* denom = sm + 20992;

    const int t0  = blockIdx.x * BMq;
    const int h   = blockIdx.y;
    const int bb_ = blockIdx.z;
    const int tid = threadIdx.x;
    const int lane = tid & 31;
    const int wid  = tid >> 5;
    const int g    = lane >> 2;
    const int tg   = lane & 3;
    const int im2  = wid >> 2;         // 0..1: row half
    const int in2  = wid & 3;          // 0..3: col quarter

    const int nch = (t0 >> 6) + 1;

    auto stage = [&](int c, int buf) {
        const int c0 = c << 6;
        unsigned* w2d = w2su + buf * 2304;
        float* vsd = vs + buf * 64 * VSS;
        const __nv_bfloat16* w2g = w2b + (size_t)h * Mq * HDq + (size_t)c0 * HDq;
        const float* vg  = gv + (size_t)bb_ * Tq * Cq + (size_t)c0 * Cq + h * HDq;
#pragma unroll
        for (int i = 0; i < 2; i++) {          // w2: 64 m-rows x 128B = 512 chunks
            int cc = tid + i * 256;
            int r  = cc >> 3;
            int ch = cc & 7;
            cp_async16(&w2d[r * W2B + ch * 4], &w2g[(size_t)r * HDq + ch * 8]);
        }
#pragma unroll
        for (int i = 0; i < 4; i++) {          // V: 64 rows x 256B = 1024 chunks
            int cc = tid + i * 256;
            int l  = cc >> 4;
            int d4 = (cc & 15) << 2;
            cp_async16(&vsd[l * VSS + d4], &vg[(size_t)l * Cq + d4]);
        }
        asm volatile("cp.async.commit_group;" ::: "memory");
    };

    {
#pragma unroll
        for (int i = 0; i < 2; i++) {          // K: 64 rows x 128B = 512 chunks
            int cc = tid + i * 256;
            int r  = cc >> 3;
            int ch = cc & 7;
            cp_async16(&ksu[r * KSB + ch * 4],
                       &gk[(size_t)(bb_ * Tq + t0 + r) * Cq + h * HDq + ch * 8]);
        }
        stage(0, 0);
    }

    float o[2][2][4];
    float dp[2][2];
#pragma unroll
    for (int i2 = 0; i2 < 2; i2++) {
#pragma unroll
        for (int in = 0; in < 2; in++)
#pragma unroll
            for (int e = 0; e < 4; e++) o[i2][in][e] = 0.f;
        dp[i2][0] = 0.f; dp[i2][1] = 0.f;
    }

    for (int c = 0; c < nch; c++) {
        const int buf = c & 1;
        if (c + 1 < nch) {
            stage(c + 1, (c + 1) & 1);
            asm volatile("cp.async.wait_group 1;" ::: "memory");
        } else {
            asm volatile("cp.async.wait_group 0;" ::: "memory");
        }
        __syncthreads();

        // ---- score mma (bf16 k16): rows [32*im2,+32) x cols [16*in2,+16) ----
        const unsigned* w2c = w2su + buf * 2304;
        float d[2][2][4];
#pragma unroll
        for (int i2 = 0; i2 < 2; i2++)
#pragma unroll
            for (int in = 0; in < 2; in++)
#pragma unroll
                for (int e = 0; e < 4; e++) d[i2][in][e] = 0.f;

#pragma unroll
        for (int kf = 0; kf < 4; kf++) {       // k16 steps over d=64
            unsigned a0[2], a1[2], a2[2], a3[2];
#pragma unroll
            for (int i2 = 0; i2 < 2; i2++) {
                int r = (im2 * 2 + i2) * 16 + g;
                a0[i2] = ksu[r * KSB + kf * 8 + tg];
                a1[i2] = ksu[(r + 8) * KSB + kf * 8 + tg];
                a2[i2] = ksu[r * KSB + kf * 8 + tg + 4];
                a3[i2] = ksu[(r + 8) * KSB + kf * 8 + tg + 4];
            }
#pragma unroll
            for (int in = 0; in < 2; in++) {
                int n = in2 * 16 + in * 8 + g;
                unsigned b0 = w2c[n * W2B + kf * 8 + tg];
                unsigned b1 = w2c[n * W2B + kf * 8 + tg + 4];
#pragma unroll
                for (int i2 = 0; i2 < 2; i2++)
                    mma_bf16(d[i2][in][0], d[i2][in][1], d[i2][in][2], d[i2][in][3],
                             a0[i2], a1[i2], a2[i2], a3[i2], b0, b1);
            }
        }

        // ---- bias + exp + causal mask + ps store + denom partials ----
#pragma unroll
        for (int in = 0; in < 2; in++) {
            const int colb = (c << 6) + in2 * 16 + in * 8 + 2 * tg;
            float2 bz = *(const float2*)&b2[colb];
            const int loc = in2 * 16 + in * 8 + 2 * tg;
#pragma unroll
            for (int i2 = 0; i2 < 2; i2++) {
                const int imt = im2 * 2 + i2;
                const int r1 = t0 + imt * 16 + g;
                const int r2 = r1 + 8;
                float s0 = d[i2][in][0] + bz.x;
                float s1 = d[i2][in][1] + bz.y;
                float s2 = d[i2][in][2] + bz.x;
                float s3 = d[i2][in][3] + bz.y;
                float e0 = (colb     <= r1) ? __expf(s0) : 0.f;
                float e1 = (colb + 1 <= r1) ? __expf(s1) : 0.f;
                float e2 = (colb     <= r2) ? __expf(s2) : 0.f;
                float e3 = (colb + 1 <= r2) ? __expf(s3) : 0.f;
                dp[i2][0] += e0 + e1;
                dp[i2][1] += e2 + e3;
                float2 p0, p1;
                p0.x = __uint_as_float(f2tf32(e0));
                p0.y = __uint_as_float(f2tf32(e1));
                p1.x = __uint_as_float(f2tf32(e2));
                p1.y = __uint_as_float(f2tf32(e3));
                *(float2*)&ps[(imt * 16 + g) * PSS + loc] = p0;
                *(float2*)&ps[(imt * 16 + 8 + g) * PSS + loc] = p1;
            }
        }
        __syncthreads();

        // ---- PV mma (tf32 k8): rows [32*im2,+32) x hd cols [16*in2,+16) ----
        const float* vc = vs + buf * 64 * VSS;
#pragma unroll
        for (int kf = 0; kf < 8; kf++) {
            const int l0 = kf * 8;
            unsigned a0[2], a1[2], a2[2], a3[2];
#pragma unroll
            for (int i2 = 0; i2 < 2; i2++) {
                int r = (im2 * 2 + i2) * 16 + g;
                a0[i2] = __float_as_uint(ps[r * PSS + l0 + tg]);
                a1[i2] = __float_as_uint(ps[(r + 8) * PSS + l0 + tg]);
                a2[i2] = __float_as_uint(ps[r * PSS + l0 + tg + 4]);
                a3[i2] = __float_as_uint(ps[(r + 8) * PSS + l0 + tg + 4]);
            }
#pragma unroll
            for (int in = 0; in < 2; in++) {
                int hd = in2 * 16 + in * 8 + g;
                unsigned b0 = __float_as_uint(vc[(l0 + tg) * VSS + hd]);
                unsigned b1 = __float_as_uint(vc[(l0 + tg + 4) * VSS + hd]);
#pragma unroll
                for (int i2 = 0; i2 < 2; i2++)
                    mma_tf32(o[i2][in][0], o[i2][in][1], o[i2][in][2], o[i2][in][3],
                             a0[i2], a1[i2], a2[i2], a3[i2], b0, b1);
            }
        }
        __syncthreads();
    }

    // ---- denominator reduction ----
#pragma unroll
    for (int i2 = 0; i2 < 2; i2++) {
#pragma unroll
        for (int hf = 0; hf < 2; hf++) {
            float v = dp[i2][hf];
            v += __shfl_xor_sync(0xffffffffu, v, 1);
            v += __shfl_xor_sync(0xffffffffu, v, 2);
            dp[i2][hf] = v;
        }
    }
    if (tg == 0) {
#pragma unroll
        for (int t = 0; t < 4; t++) {
            float v0 = 0.f, v1 = 0.f;
            if ((t >> 1) == im2) {
                v0 = dp[t & 1][0];
                v1 = dp[t & 1][1];
            }
            dpart[wid * 64 + t * 16 + g]     = v0;
            dpart[wid * 64 + t * 16 + 8 + g] = v1;
        }
    }
    __syncthreads();
    if (tid < 64) {
        float s = 0.f;
#pragma unroll
        for (int w = 0; w < 8; w++) s += dpart[w * 64 + tid];
        denom[tid] = 1.f / s;
    }
    __syncthreads();

    // ---- output: y as bf16 hi/lo planes ----
#pragma unroll
    for (int i2 = 0; i2 < 2; i2++) {
        const int imt = im2 * 2 + i2;
        const int r = imt * 16 + g;
        const float iv1 = denom[r];
        const float iv2 = denom[r + 8];
#pragma unroll
        for (int in = 0; in < 2; in++) {
            float y0 = o[i2][in][0] * iv1, y1 = o[i2][in][1] * iv1;
            float y2 = o[i2][in][2] * iv2, y3 = o[i2][in][3] * iv2;
            __nv_bfloat16 h0, l0, h1, l1, h2, l2, h3, l3;
            bf16_split(y0, h0, l0); bf16_split(y1, h1, l1);
            bf16_split(y2, h2, l2); bf16_split(y3, h3, l3);
            const int cb = h * HDq + in2 * 16 + in * 8 + 2 * tg;
            size_t off1 = (size_t)(bb_ * Tq + t0 + r) * Cq + cb;
            size_t off2 = (size_t)(bb_ * Tq + t0 + r + 8) * Cq + cb;
            __nv_bfloat162 ph0; ph0.x = h0; ph0.y = h1;
            __nv_bfloat162 pl0; pl0.x = l0; pl0.y = l1;
            __nv_bfloat162 ph1; ph1.x = h2; ph1.y = h3;
            __nv_bfloat162 pl1; pl1.x = l2; pl1.y = l3;
            *(__nv_bfloat162*)&yhi[off1] = ph0;
            *(__nv_bfloat162*)&ylo[off1] = pl0;
            *(__nv_bfloat162*)&yhi[off2] = ph1;
            *(__nv_bfloat162*)&ylo[off2] = pl1;
        }
    }
}

// ---------------------------------------------------------------------------
extern "C" void kernel_launch(void* const* d_in, const int* in_sizes, int n_in,
                              void* d_out, int out_size)
{
    const float* x       = (const float*)d_in[0];
    const float* w1_w    = (const float*)d_in[1];
    const float* w1_b    = (const float*)d_in[2];
    const float* w2      = (const float*)d_in[3];
    const float* b2      = (const float*)d_in[4];
    const float* value_w = (const float*)d_in[5];
    const float* value_b = (const float*)d_in[6];
    const float* proj_w  = (const float*)d_in[7];
    const float* proj_b  = (const float*)d_in[8];
    float* out = (float*)d_out;

    float *pv;
    __nv_bfloat16 *pkb, *pw2b;
    __nv_bfloat16 *pahi, *palo, *pw1hi, *pw1lo, *pvwhi, *pvwlo, *ppwhi, *ppwlo;
    cudaGetSymbolAddress((void**)&pkb,   g_kb);
    cudaGetSymbolAddress((void**)&pv,    g_v);
    cudaGetSymbolAddress((void**)&pw2b,  g_w2b);
    cudaGetSymbolAddress((void**)&pahi,  g_ahi);
    cudaGetSymbolAddress((void**)&palo,  g_alo);
    cudaGetSymbolAddress((void**)&pw1hi, g_w1hi);
    cudaGetSymbolAddress((void**)&pw1lo, g_w1lo);
    cudaGetSymbolAddress((void**)&pvwhi, g_vwhi);
    cudaGetSymbolAddress((void**)&pvwlo, g_vwlo);
    cudaGetSymbolAddress((void**)&ppwhi, g_pwhi);
    cudaGetSymbolAddress((void**)&ppwlo, g_pwlo);

    const int SMEM_GEMM = 8 * PLW * (int)sizeof(unsigned);      // 80 KB
    const int SMEM_ATTN = ATTN_WORDS * (int)sizeof(float);      // ~82 KB
    cudaFuncSetAttribute(gemm_bf16_kernel<true, 2>,
                         cudaFuncAttributeMaxDynamicSharedMemorySize, SMEM_GEMM);
    cudaFuncSetAttribute(gemm_bf16_kernel<false, 1>,
                         cudaFuncAttributeMaxDynamicSharedMemorySize, SMEM_GEMM);
    cudaFuncSetAttribute(gemm_bf16_kernel<false, 0>,
                         cudaFuncAttributeMaxDynamicSharedMemorySize, SMEM_GEMM);
    cudaFuncSetAttribute(attn2_kernel,
                         cudaFuncAttributeMaxDynamicSharedMemorySize, SMEM_ATTN);

    const int Mrows = Bq * Tq;                 // 4096
    dim3 gemm_grid(Cq / 128, Mrows / 128);     // (8, 32)

    // prep: x + weight splits, and w2 transpose->bf16
    prep_kernel<<<PREP_TOTAL / 256, 256>>>(
        (const float4*)x, (const float4*)w1_w, (const float4*)value_w,
        (const float4*)proj_w,
        (__nv_bfloat162*)pahi,  (__nv_bfloat162*)palo,
        (__nv_bfloat162*)pw1hi, (__nv_bfloat162*)pw1lo,
        (__nv_bfloat162*)pvwhi, (__nv_bfloat162*)pvwlo,
        (__nv_bfloat162*)ppwhi, (__nv_bfloat162*)ppwlo);
    {
        dim3 tgrid(Mq / 64, Hq);
        w2t_kernel<<<tgrid, 256>>>(w2, pw2b);
    }

    // k = relu(x @ w1^T + b1) -> bf16
    gemm_bf16_kernel<true, 2><<<gemm_grid, 256, SMEM_GEMM>>>(
        pahi, palo, pw1hi, pw1lo, w1_b, pkb, Mrows, Cq, Cq);

    // v = x @ value^T + vb -> tf32-rounded fp32
    gemm_bf16_kernel<false, 1><<<gemm_grid, 256, SMEM_GEMM>>>(
        pahi, palo, pvwhi, pvwlo, value_b, pv, Mrows, Cq, Cq);

    // attention: writes y bf16 hi/lo planes (overwrites x planes)
    dim3 agrid(Tq / BMq, Hq, Bq);              // (32, 16, 2)
    attn2_kernel<<<agrid, 256, SMEM_ATTN>>>(pkb, pv, pw2b, b2, pahi, palo);

    // out = y @ proj^T + pb (fp32 output)
    gemm_bf16_kernel<false, 0><<<gemm_grid, 256, SMEM_GEMM>>>(
        pahi, palo, ppwhi, ppwlo, proj_b, out, Mrows, Cq, Cq);
}

// round 17
// speedup vs baseline: 1.3123x; 1.1110x over previous
#include <cuda_runtime.h>
#include <cuda_bf16.h>
#include <math.h>

// Problem constants
#define Bq   2
#define Tq   2048
#define Cq   1024
#define Hq   16
#define HDq  64
#define Mq   2048

// Scratch (allocation-free rule: __device__ globals)
__device__ __nv_bfloat16 g_kb[Bq * Tq * Cq];   // relu(x@w1^T+b1), bf16
__device__ float         g_v[Bq * Tq * Cq];    // x@value^T+vb, tf32-rounded
__device__ __nv_bfloat16 g_ahi[Bq * Tq * Cq];  // activation hi plane (x, then y)
__device__ __nv_bfloat16 g_alo[Bq * Tq * Cq];  // activation lo plane
__device__ __nv_bfloat16 g_w1hi[Cq * Cq];      // w1 hi plane (single-term k GEMM)
__device__ __nv_bfloat16 g_vwhi[Cq * Cq];      // value_w hi plane
__device__ __nv_bfloat16 g_vwlo[Cq * Cq];      // value_w lo plane
__device__ __nv_bfloat16 g_pwhi[Cq * Cq];      // proj_w hi plane
__device__ __nv_bfloat16 g_pwlo[Cq * Cq];      // proj_w lo plane
__device__ __nv_bfloat16 g_w2b[Hq * Mq * HDq]; // w2 transposed bf16: [h][m][d]

// ---------------------------------------------------------------------------
// helpers
// ---------------------------------------------------------------------------
__device__ __forceinline__ unsigned f2tf32(float x) {
    unsigned u;
    asm("cvt.rna.tf32.f32 %0, %1;" : "=r"(u) : "f"(x));
    return u;
}

__device__ __forceinline__ void mma_tf32(
    float& d0, float& d1, float& d2, float& d3,
    unsigned a0, unsigned a1, unsigned a2, unsigned a3,
    unsigned b0, unsigned b1)
{
    asm volatile(
        "mma.sync.aligned.m16n8k8.row.col.f32.tf32.tf32.f32 "
        "{%0,%1,%2,%3}, {%4,%5,%6,%7}, {%8,%9}, {%0,%1,%2,%3};"
        : "+f"(d0), "+f"(d1), "+f"(d2), "+f"(d3)
        : "r"(a0), "r"(a1), "r"(a2), "r"(a3), "r"(b0), "r"(b1));
}

__device__ __forceinline__ void mma_bf16(
    float& d0, float& d1, float& d2, float& d3,
    unsigned a0, unsigned a1, unsigned a2, unsigned a3,
    unsigned b0, unsigned b1)
{
    asm volatile(
        "mma.sync.aligned.m16n8k16.row.col.f32.bf16.bf16.f32 "
        "{%0,%1,%2,%3}, {%4,%5,%6,%7}, {%8,%9}, {%0,%1,%2,%3};"
        : "+f"(d0), "+f"(d1), "+f"(d2), "+f"(d3)
        : "r"(a0), "r"(a1), "r"(a2), "r"(a3), "r"(b0), "r"(b1));
}

__device__ __forceinline__ void cp_async16(void* s, const void* g) {
    unsigned sa = (unsigned)__cvta_generic_to_shared(s);
    asm volatile("cp.async.cg.shared.global [%0], [%1], 16;" :: "r"(sa), "l"(g));
}

__device__ __forceinline__ void bf16_split(float v, __nv_bfloat16& h, __nv_bfloat16& l) {
    h = __float2bfloat16_rn(v);
    l = __float2bfloat16_rn(v - __bfloat162float(h));
}

// ---------------------------------------------------------------------------
// Fused prep kernel: x split, w1 hi-only, value/proj splits
// ---------------------------------------------------------------------------
#define NACT4 ((Bq * Tq * Cq) / 4)
#define NW4   ((Cq * Cq) / 4)
#define PREP_TOTAL (NACT4 + 3 * NW4)

__device__ __forceinline__ void split4_store(
    float4 v, __nv_bfloat162* hi, __nv_bfloat162* lo, int i)
{
    __nv_bfloat16 hx, lx, hy, ly, hz, lz, hw, lw;
    bf16_split(v.x, hx, lx);
    bf16_split(v.y, hy, ly);
    bf16_split(v.z, hz, lz);
    bf16_split(v.w, hw, lw);
    __nv_bfloat162 h0; h0.x = hx; h0.y = hy;
    __nv_bfloat162 h1; h1.x = hz; h1.y = hw;
    __nv_bfloat162 l0; l0.x = lx; l0.y = ly;
    __nv_bfloat162 l1; l1.x = lz; l1.y = lw;
    hi[2 * i] = h0; hi[2 * i + 1] = h1;
    lo[2 * i] = l0; lo[2 * i + 1] = l1;
}

__global__ __launch_bounds__(256) void prep_kernel(
    const float4* __restrict__ x,  const float4* __restrict__ w1,
    const float4* __restrict__ vw, const float4* __restrict__ pw,
    __nv_bfloat162* __restrict__ ahi,  __nv_bfloat162* __restrict__ alo,
    __nv_bfloat162* __restrict__ w1hi,
    __nv_bfloat162* __restrict__ vwhi, __nv_bfloat162* __restrict__ vwlo,
    __nv_bfloat162* __restrict__ pwhi, __nv_bfloat162* __restrict__ pwlo)
{
    int gi = blockIdx.x * 256 + threadIdx.x;
    if (gi < NACT4) {
        split4_store(x[gi], ahi, alo, gi);
    } else if (gi < NACT4 + NW4) {
        int i = gi - NACT4;
        float4 v = w1[i];
        __nv_bfloat162 h0, h1;
        h0.x = __float2bfloat16_rn(v.x); h0.y = __float2bfloat16_rn(v.y);
        h1.x = __float2bfloat16_rn(v.z); h1.y = __float2bfloat16_rn(v.w);
        w1hi[2 * i] = h0; w1hi[2 * i + 1] = h1;
    } else if (gi < NACT4 + 2 * NW4) {
        int i = gi - (NACT4 + NW4);
        split4_store(vw[i], vwhi, vwlo, i);
    } else {
        int i = gi - (NACT4 + 2 * NW4);
        split4_store(pw[i], pwhi, pwlo, i);
    }
}

// w2 transpose + bf16: [h][d][m] fp32 -> [h][m][d] bf16 via 64x64 smem tiles
__global__ __launch_bounds__(256) void w2t_kernel(
    const float* __restrict__ w2, __nv_bfloat16* __restrict__ w2b)
{
    __shared__ float t[64][65];
    const int h  = blockIdx.y;
    const int m0 = blockIdx.x * 64;
    const int tid = threadIdx.x;
#pragma unroll
    for (int i = 0; i < 16; i++) {
        int idx = tid + i * 256;
        int d = idx >> 6, m = idx & 63;
        t[d][m] = w2[(size_t)h * HDq * Mq + (size_t)d * Mq + m0 + m];
    }
    __syncthreads();
#pragma unroll
    for (int i = 0; i < 16; i++) {
        int idx = tid + i * 256;
        int m = idx >> 6, d = idx & 63;
        w2b[(size_t)h * Mq * HDq + (size_t)(m0 + m) * HDq + d] =
            __float2bfloat16_rn(t[d][m]);
    }
}

// ---------------------------------------------------------------------------
// Dense GEMM, 3x bf16 hi/lo (proven): cp.async 2-stage, 2 CTAs/SM
// OMODE: 0 = fp32 out, 1 = tf32-rounded fp32 out
// ---------------------------------------------------------------------------
#define ST   20
#define PLW  2560

template <int OMODE>
__global__ __launch_bounds__(256, 2) void gemm_bf16_kernel(
    const __nv_bfloat16* __restrict__ Ahi, const __nv_bfloat16* __restrict__ Alo,
    const __nv_bfloat16* __restrict__ Whi, const __nv_bfloat16* __restrict__ Wlo,
    const float* __restrict__ bias, float* __restrict__ Cmat,
    int Mdim, int Ndim, int Kdim)
{
    extern __shared__ unsigned smu[];
    unsigned* sAh = smu;
    unsigned* sAl = sAh + 2 * PLW;
    unsigned* sBh = sAl + 2 * PLW;
    unsigned* sBl = sBh + 2 * PLW;

    const int tid  = threadIdx.x;
    const int lane = tid & 31;
    const int wid  = tid >> 5;
    const int wm   = (wid & 3) * 32;
    const int wn   = (wid >> 2) * 64;
    const int g    = lane >> 2;
    const int tg   = lane & 3;

    const int m0 = blockIdx.y * 128;
    const int n0 = blockIdx.x * 128;
    const int NK = Kdim >> 5;

    float acc[2][8][4];
#pragma unroll
    for (int im = 0; im < 2; im++)
#pragma unroll
        for (int in = 0; in < 8; in++)
#pragma unroll
            for (int e = 0; e < 4; e++) acc[im][in][e] = 0.f;

    auto load_stage = [&](int kt, int st) {
        const int k0 = kt << 5;
#pragma unroll
        for (int i = 0; i < 8; i++) {
            int cc = tid + (i & 1) * 256;
            int r  = cc >> 2;
            int j  = cc & 3;
            if ((i >> 1) == 0)
                cp_async16(&sAh[st * PLW + r * ST + 4 * j],
                           &Ahi[(size_t)(m0 + r) * Kdim + k0 + 8 * j]);
            else if ((i >> 1) == 1)
                cp_async16(&sAl[st * PLW + r * ST + 4 * j],
                           &Alo[(size_t)(m0 + r) * Kdim + k0 + 8 * j]);
            else if ((i >> 1) == 2)
                cp_async16(&sBh[st * PLW + r * ST + 4 * j],
                           &Whi[(size_t)(n0 + r) * Kdim + k0 + 8 * j]);
            else
                cp_async16(&sBl[st * PLW + r * ST + 4 * j],
                           &Wlo[(size_t)(n0 + r) * Kdim + k0 + 8 * j]);
        }
        asm volatile("cp.async.commit_group;" ::: "memory");
    };

    load_stage(0, 0);

    for (int kt = 0; kt < NK; kt++) {
        const int cur = kt & 1;
        if (kt + 1 < NK) {
            load_stage(kt + 1, (kt + 1) & 1);
            asm volatile("cp.async.wait_group 1;" ::: "memory");
        } else {
            asm volatile("cp.async.wait_group 0;" ::: "memory");
        }
        __syncthreads();

        const unsigned* pAh = sAh + cur * PLW;
        const unsigned* pAl = sAl + cur * PLW;
        const unsigned* pBh = sBh + cur * PLW;
        const unsigned* pBl = sBl + cur * PLW;

#pragma unroll
        for (int kw = 0; kw < 16; kw += 8) {
            unsigned ah[2][4], al[2][4];
#pragma unroll
            for (int im = 0; im < 2; im++) {
                int r = wm + im * 16 + g;
                ah[im][0] = pAh[r * ST + kw + tg];
                ah[im][1] = pAh[(r + 8) * ST + kw + tg];
                ah[im][2] = pAh[r * ST + kw + tg + 4];
                ah[im][3] = pAh[(r + 8) * ST + kw + tg + 4];
                al[im][0] = pAl[r * ST + kw + tg];
                al[im][1] = pAl[(r + 8) * ST + kw + tg];
                al[im][2] = pAl[r * ST + kw + tg + 4];
                al[im][3] = pAl[(r + 8) * ST + kw + tg + 4];
            }
#pragma unroll
            for (int in = 0; in < 8; in++) {
                int c = wn + in * 8 + g;
                unsigned bh0 = pBh[c * ST + kw + tg];
                unsigned bh1 = pBh[c * ST + kw + tg + 4];
                unsigned bl0 = pBl[c * ST + kw + tg];
                unsigned bl1 = pBl[c * ST + kw + tg + 4];
#pragma unroll
                for (int im = 0; im < 2; im++) {
                    float* d = acc[im][in];
                    mma_bf16(d[0], d[1], d[2], d[3],
                             ah[im][0], ah[im][1], ah[im][2], ah[im][3],
                             bh0, bh1);
                    mma_bf16(d[0], d[1], d[2], d[3],
                             ah[im][0], ah[im][1], ah[im][2], ah[im][3],
                             bl0, bl1);
                    mma_bf16(d[0], d[1], d[2], d[3],
                             al[im][0], al[im][1], al[im][2], al[im][3],
                             bh0, bh1);
                }
            }
        }
        __syncthreads();
    }

#pragma unroll
    for (int in = 0; in < 8; in++) {
        int col = n0 + wn + in * 8 + 2 * tg;
        float2 bz = *(const float2*)&bias[col];
#pragma unroll
        for (int im = 0; im < 2; im++) {
            int row = m0 + wm + im * 16 + g;
            float v0 = acc[im][in][0] + bz.x;
            float v1 = acc[im][in][1] + bz.y;
            float v2 = acc[im][in][2] + bz.x;
            float v3 = acc[im][in][3] + bz.y;
            if (OMODE == 1) {
                v0 = __uint_as_float(f2tf32(v0));
                v1 = __uint_as_float(f2tf32(v1));
                v2 = __uint_as_float(f2tf32(v2));
                v3 = __uint_as_float(f2tf32(v3));
            }
            float2 p0; p0.x = v0; p0.y = v1;
            float2 p1; p1.x = v2; p1.y = v3;
            *(float2*)&Cmat[(size_t)row * Ndim + col] = p0;
            *(float2*)&Cmat[(size_t)(row + 8) * Ndim + col] = p1;
        }
    }
}

// ---------------------------------------------------------------------------
// Single-term bf16 GEMM (k only): C_bf16 = relu(A @ W^T + bias)
// 2 planes, 2-stage cp.async, 2 CTAs/SM, 1 mma per fragment pair.
// ---------------------------------------------------------------------------
__global__ __launch_bounds__(256, 2) void gemm_bf16_1t_kernel(
    const __nv_bfloat16* __restrict__ Ah, const __nv_bfloat16* __restrict__ Wh,
    const float* __restrict__ bias, __nv_bfloat16* __restrict__ Cb,
    int Mdim, int Ndim, int Kdim)
{
    extern __shared__ unsigned smu[];
    unsigned* sA = smu;                    // [2][PLW]
    unsigned* sB = sA + 2 * PLW;

    const int tid  = threadIdx.x;
    const int lane = tid & 31;
    const int wid  = tid >> 5;
    const int wm   = (wid & 3) * 32;
    const int wn   = (wid >> 2) * 64;
    const int g    = lane >> 2;
    const int tg   = lane & 3;

    const int m0 = blockIdx.y * 128;
    const int n0 = blockIdx.x * 128;
    const int NK = Kdim >> 5;

    float acc[2][8][4];
#pragma unroll
    for (int im = 0; im < 2; im++)
#pragma unroll
        for (int in = 0; in < 8; in++)
#pragma unroll
            for (int e = 0; e < 4; e++) acc[im][in][e] = 0.f;

    auto load_stage = [&](int kt, int st) {
        const int k0 = kt << 5;
#pragma unroll
        for (int i = 0; i < 4; i++) {
            int cc = tid + (i & 1) * 256;   // 0..511
            int r  = cc >> 2;
            int j  = cc & 3;
            if ((i >> 1) == 0)
                cp_async16(&sA[st * PLW + r * ST + 4 * j],
                           &Ah[(size_t)(m0 + r) * Kdim + k0 + 8 * j]);
            else
                cp_async16(&sB[st * PLW + r * ST + 4 * j],
                           &Wh[(size_t)(n0 + r) * Kdim + k0 + 8 * j]);
        }
        asm volatile("cp.async.commit_group;" ::: "memory");
    };

    load_stage(0, 0);

    for (int kt = 0; kt < NK; kt++) {
        const int cur = kt & 1;
        if (kt + 1 < NK) {
            load_stage(kt + 1, (kt + 1) & 1);
            asm volatile("cp.async.wait_group 1;" ::: "memory");
        } else {
            asm volatile("cp.async.wait_group 0;" ::: "memory");
        }
        __syncthreads();

        const unsigned* pA = sA + cur * PLW;
        const unsigned* pB = sB + cur * PLW;

#pragma unroll
        for (int kw = 0; kw < 16; kw += 8) {
            unsigned a[2][4];
#pragma unroll
            for (int im = 0; im < 2; im++) {
                int r = wm + im * 16 + g;
                a[im][0] = pA[r * ST + kw + tg];
                a[im][1] = pA[(r + 8) * ST + kw + tg];
                a[im][2] = pA[r * ST + kw + tg + 4];
                a[im][3] = pA[(r + 8) * ST + kw + tg + 4];
            }
#pragma unroll
            for (int in = 0; in < 8; in++) {
                int c = wn + in * 8 + g;
                unsigned b0 = pB[c * ST + kw + tg];
                unsigned b1 = pB[c * ST + kw + tg + 4];
#pragma unroll
                for (int im = 0; im < 2; im++) {
                    float* d = acc[im][in];
                    mma_bf16(d[0], d[1], d[2], d[3],
                             a[im][0], a[im][1], a[im][2], a[im][3], b0, b1);
                }
            }
        }
        __syncthreads();
    }

#pragma unroll
    for (int in = 0; in < 8; in++) {
        int col = n0 + wn + in * 8 + 2 * tg;
        float2 bz = *(const float2*)&bias[col];
#pragma unroll
        for (int im = 0; im < 2; im++) {
            int row = m0 + wm + im * 16 + g;
            float v0 = fmaxf(acc[im][in][0] + bz.x, 0.f);
            float v1 = fmaxf(acc[im][in][1] + bz.y, 0.f);
            float v2 = fmaxf(acc[im][in][2] + bz.x, 0.f);
            float v3 = fmaxf(acc[im][in][3] + bz.y, 0.f);
            __nv_bfloat162 p0, p1;
            p0.x = __float2bfloat16_rn(v0); p0.y = __float2bfloat16_rn(v1);
            p1.x = __float2bfloat16_rn(v2); p1.y = __float2bfloat16_rn(v3);
            *(__nv_bfloat162*)&Cb[(size_t)row * Ndim + col] = p0;
            *(__nv_bfloat162*)&Cb[(size_t)(row + 8) * Ndim + col] = p1;
        }
    }
}

// ---------------------------------------------------------------------------
// Chunked fused attention (R16, proven): bf16 score, tf32 PV, warp tile 32x16
// ---------------------------------------------------------------------------
#define BMq   64
#define KSB   36
#define W2B   36
#define VSS   72
#define PSS   68
#define ATTN_WORDS 21056

__global__ __launch_bounds__(256, 2) void attn2_kernel(
    const __nv_bfloat16* __restrict__ gk, const float* __restrict__ gv,
    const __nv_bfloat16* __restrict__ w2b, const float* __restrict__ b2,
    __nv_bfloat16* __restrict__ yhi, __nv_bfloat16* __restrict__ ylo)
{
    extern __shared__ float sm[];
    unsigned* ksu  = (unsigned*)sm;
    unsigned* w2su = (unsigned*)sm + 2304;
    float* vs    = sm + 6912;
    float* ps    = sm + 16128;
    float* dpart = sm + 20480;
    float* denom = sm + 20992;

    const int t0  = blockIdx.x * BMq;
    const int h   = blockIdx.y;
    const int bb_ = blockIdx.z;
    const int tid = threadIdx.x;
    const int lane = tid & 31;
    const int wid  = tid >> 5;
    const int g    = lane >> 2;
    const int tg   = lane & 3;
    const int im2  = wid >> 2;
    const int in2  = wid & 3;

    const int nch = (t0 >> 6) + 1;

    auto stage = [&](int c, int buf) {
        const int c0 = c << 6;
        unsigned* w2d = w2su + buf * 2304;
        float* vsd = vs + buf * 64 * VSS;
        const __nv_bfloat16* w2g = w2b + (size_t)h * Mq * HDq + (size_t)c0 * HDq;
        const float* vg  = gv + (size_t)bb_ * Tq * Cq + (size_t)c0 * Cq + h * HDq;
#pragma unroll
        for (int i = 0; i < 2; i++) {
            int cc = tid + i * 256;
            int r  = cc >> 3;
            int ch = cc & 7;
            cp_async16(&w2d[r * W2B + ch * 4], &w2g[(size_t)r * HDq + ch * 8]);
        }
#pragma unroll
        for (int i = 0; i < 4; i++) {
            int cc = tid + i * 256;
            int l  = cc >> 4;
            int d4 = (cc & 15) << 2;
            cp_async16(&vsd[l * VSS + d4], &vg[(size_t)l * Cq + d4]);
        }
        asm volatile("cp.async.commit_group;" ::: "memory");
    };

    {
#pragma unroll
        for (int i = 0; i < 2; i++) {
            int cc = tid + i * 256;
            int r  = cc >> 3;
            int ch = cc & 7;
            cp_async16(&ksu[r * KSB + ch * 4],
                       &gk[(size_t)(bb_ * Tq + t0 + r) * Cq + h * HDq + ch * 8]);
        }
        stage(0, 0);
    }

    float o[2][2][4];
    float dp[2][2];
#pragma unroll
    for (int i2 = 0; i2 < 2; i2++) {
#pragma unroll
        for (int in = 0; in < 2; in++)
#pragma unroll
            for (int e = 0; e < 4; e++) o[i2][in][e] = 0.f;
        dp[i2][0] = 0.f; dp[i2][1] = 0.f;
    }

    for (int c = 0; c < nch; c++) {
        const int buf = c & 1;
        if (c + 1 < nch) {
            stage(c + 1, (c + 1) & 1);
            asm volatile("cp.async.wait_group 1;" ::: "memory");
        } else {
            asm volatile("cp.async.wait_group 0;" ::: "memory");
        }
        __syncthreads();

        const unsigned* w2c = w2su + buf * 2304;
        float d[2][2][4];
#pragma unroll
        for (int i2 = 0; i2 < 2; i2++)
#pragma unroll
            for (int in = 0; in < 2; in++)
#pragma unroll
                for (int e = 0; e < 4; e++) d[i2][in][e] = 0.f;

#pragma unroll
        for (int kf = 0; kf < 4; kf++) {
            unsigned a0[2], a1[2], a2[2], a3[2];
#pragma unroll
            for (int i2 = 0; i2 < 2; i2++) {
                int r = (im2 * 2 + i2) * 16 + g;
                a0[i2] = ksu[r * KSB + kf * 8 + tg];
                a1[i2] = ksu[(r + 8) * KSB + kf * 8 + tg];
                a2[i2] = ksu[r * KSB + kf * 8 + tg + 4];
                a3[i2] = ksu[(r + 8) * KSB + kf * 8 + tg + 4];
            }
#pragma unroll
            for (int in = 0; in < 2; in++) {
                int n = in2 * 16 + in * 8 + g;
                unsigned b0 = w2c[n * W2B + kf * 8 + tg];
                unsigned b1 = w2c[n * W2B + kf * 8 + tg + 4];
#pragma unroll
                for (int i2 = 0; i2 < 2; i2++)
                    mma_bf16(d[i2][in][0], d[i2][in][1], d[i2][in][2], d[i2][in][3],
                             a0[i2], a1[i2], a2[i2], a3[i2], b0, b1);
            }
        }

#pragma unroll
        for (int in = 0; in < 2; in++) {
            const int colb = (c << 6) + in2 * 16 + in * 8 + 2 * tg;
            float2 bz = *(const float2*)&b2[colb];
            const int loc = in2 * 16 + in * 8 + 2 * tg;
#pragma unroll
            for (int i2 = 0; i2 < 2; i2++) {
                const int imt = im2 * 2 + i2;
                const int r1 = t0 + imt * 16 + g;
                const int r2 = r1 + 8;
                float s0 = d[i2][in][0] + bz.x;
                float s1 = d[i2][in][1] + bz.y;
                float s2 = d[i2][in][2] + bz.x;
                float s3 = d[i2][in][3] + bz.y;
                float e0 = (colb     <= r1) ? __expf(s0) : 0.f;
                float e1 = (colb + 1 <= r1) ? __expf(s1) : 0.f;
                float e2 = (colb     <= r2) ? __expf(s2) : 0.f;
                float e3 = (colb + 1 <= r2) ? __expf(s3) : 0.f;
                dp[i2][0] += e0 + e1;
                dp[i2][1] += e2 + e3;
                float2 p0, p1;
                p0.x = __uint_as_float(f2tf32(e0));
                p0.y = __uint_as_float(f2tf32(e1));
                p1.x = __uint_as_float(f2tf32(e2));
                p1.y = __uint_as_float(f2tf32(e3));
                *(float2*)&ps[(imt * 16 + g) * PSS + loc] = p0;
                *(float2*)&ps[(imt * 16 + 8 + g) * PSS + loc] = p1;
            }
        }
        __syncthreads();

        const float* vc = vs + buf * 64 * VSS;
#pragma unroll
        for (int kf = 0; kf < 8; kf++) {
            const int l0 = kf * 8;
            unsigned a0[2], a1[2], a2[2], a3[2];
#pragma unroll
            for (int i2 = 0; i2 < 2; i2++) {
                int r = (im2 * 2 + i2) * 16 + g;
                a0[i2] = __float_as_uint(ps[r * PSS + l0 + tg]);
                a1[i2] = __float_as_uint(ps[(r + 8) * PSS + l0 + tg]);
                a2[i2] = __float_as_uint(ps[r * PSS + l0 + tg + 4]);
                a3[i2] = __float_as_uint(ps[(r + 8) * PSS + l0 + tg + 4]);
            }
#pragma unroll
            for (int in = 0; in < 2; in++) {
                int hd = in2 * 16 + in * 8 + g;
                unsigned b0 = __float_as_uint(vc[(l0 + tg) * VSS + hd]);
                unsigned b1 = __float_as_uint(vc[(l0 + tg + 4) * VSS + hd]);
#pragma unroll
                for (int i2 = 0; i2 < 2; i2++)
                    mma_tf32(o[i2][in][0], o[i2][in][1], o[i2][in][2], o[i2][in][3],
                             a0[i2], a1[i2], a2[i2], a3[i2], b0, b1);
            }
        }
        __syncthreads();
    }

#pragma unroll
    for (int i2 = 0; i2 < 2; i2++) {
#pragma unroll
        for (int hf = 0; hf < 2; hf++) {
            float v = dp[i2][hf];
            v += __shfl_xor_sync(0xffffffffu, v, 1);
            v += __shfl_xor_sync(0xffffffffu, v, 2);
            dp[i2][hf] = v;
        }
    }
    if (tg == 0) {
#pragma unroll
        for (int t = 0; t < 4; t++) {
            float v0 = 0.f, v1 = 0.f;
            if ((t >> 1) == im2) {
                v0 = dp[t & 1][0];
                v1 = dp[t & 1][1];
            }
            dpart[wid * 64 + t * 16 + g]     = v0;
            dpart[wid * 64 + t * 16 + 8 + g] = v1;
        }
    }
    __syncthreads();
    if (tid < 64) {
        float s = 0.f;
#pragma unroll
        for (int w = 0; w < 8; w++) s += dpart[w * 64 + tid];
        denom[tid] = 1.f / s;
    }
    __syncthreads();

#pragma unroll
    for (int i2 = 0; i2 < 2; i2++) {
        const int imt = im2 * 2 + i2;
        const int r = imt * 16 + g;
        const float iv1 = denom[r];
        const float iv2 = denom[r + 8];
#pragma unroll
        for (int in = 0; in < 2; in++) {
            float y0 = o[i2][in][0] * iv1, y1 = o[i2][in][1] * iv1;
            float y2 = o[i2][in][2] * iv2, y3 = o[i2][in][3] * iv2;
            __nv_bfloat16 h0, l0, h1, l1, h2, l2, h3, l3;
            bf16_split(y0, h0, l0); bf16_split(y1, h1, l1);
            bf16_split(y2, h2, l2); bf16_split(y3, h3, l3);
            const int cb = h * HDq + in2 * 16 + in * 8 + 2 * tg;
            size_t off1 = (size_t)(bb_ * Tq + t0 + r) * Cq + cb;
            size_t off2 = (size_t)(bb_ * Tq + t0 + r + 8) * Cq + cb;
            __nv_bfloat162 ph0; ph0.x = h0; ph0.y = h1;
            __nv_bfloat162 pl0; pl0.x = l0; pl0.y = l1;
            __nv_bfloat162 ph1; ph1.x = h2; ph1.y = h3;
            __nv_bfloat162 pl1; pl1.x = l2; pl1.y = l3;
            *(__nv_bfloat162*)&yhi[off1] = ph0;
            *(__nv_bfloat162*)&ylo[off1] = pl0;
            *(__nv_bfloat162*)&yhi[off2] = ph1;
            *(__nv_bfloat162*)&ylo[off2] = pl1;
        }
    }
}

// ---------------------------------------------------------------------------
extern "C" void kernel_launch(void* const* d_in, const int* in_sizes, int n_in,
                              void* d_out, int out_size)
{
    const float* x       = (const float*)d_in[0];
    const float* w1_w    = (const float*)d_in[1];
    const float* w1_b    = (const float*)d_in[2];
    const float* w2      = (const float*)d_in[3];
    const float* b2      = (const float*)d_in[4];
    const float* value_w = (const float*)d_in[5];
    const float* value_b = (const float*)d_in[6];
    const float* proj_w  = (const float*)d_in[7];
    const float* proj_b  = (const float*)d_in[8];
    float* out = (float*)d_out;

    float *pv;
    __nv_bfloat16 *pkb, *pw2b;
    __nv_bfloat16 *pahi, *palo, *pw1hi, *pvwhi, *pvwlo, *ppwhi, *ppwlo;
    cudaGetSymbolAddress((void**)&pkb,   g_kb);
    cudaGetSymbolAddress((void**)&pv,    g_v);
    cudaGetSymbolAddress((void**)&pw2b,  g_w2b);
    cudaGetSymbolAddress((void**)&pahi,  g_ahi);
    cudaGetSymbolAddress((void**)&palo,  g_alo);
    cudaGetSymbolAddress((void**)&pw1hi, g_w1hi);
    cudaGetSymbolAddress((void**)&pvwhi, g_vwhi);
    cudaGetSymbolAddress((void**)&pvwlo, g_vwlo);
    cudaGetSymbolAddress((void**)&ppwhi, g_pwhi);
    cudaGetSymbolAddress((void**)&ppwlo, g_pwlo);

    const int SMEM_GEMM  = 8 * PLW * (int)sizeof(unsigned);     // 80 KB
    const int SMEM_GEMM1 = 4 * PLW * (int)sizeof(unsigned);     // 40 KB
    const int SMEM_ATTN  = ATTN_WORDS * (int)sizeof(float);     // ~82 KB
    cudaFuncSetAttribute(gemm_bf16_kernel<1>,
                         cudaFuncAttributeMaxDynamicSharedMemorySize, SMEM_GEMM);
    cudaFuncSetAttribute(gemm_bf16_kernel<0>,
                         cudaFuncAttributeMaxDynamicSharedMemorySize, SMEM_GEMM);
    cudaFuncSetAttribute(gemm_bf16_1t_kernel,
                         cudaFuncAttributeMaxDynamicSharedMemorySize, SMEM_GEMM1);
    cudaFuncSetAttribute(attn2_kernel,
                         cudaFuncAttributeMaxDynamicSharedMemorySize, SMEM_ATTN);

    const int Mrows = Bq * Tq;                 // 4096
    dim3 gemm_grid(Cq / 128, Mrows / 128);     // (8, 32)

    // prep: x split, w1 hi-only, value/proj splits; w2 transpose->bf16
    prep_kernel<<<PREP_TOTAL / 256, 256>>>(
        (const float4*)x, (const float4*)w1_w, (const float4*)value_w,
        (const float4*)proj_w,
        (__nv_bfloat162*)pahi,  (__nv_bfloat162*)palo,
        (__nv_bfloat162*)pw1hi,
        (__nv_bfloat162*)pvwhi, (__nv_bfloat162*)pvwlo,
        (__nv_bfloat162*)ppwhi, (__nv_bfloat162*)ppwlo);
    {
        dim3 tgrid(Mq / 64, Hq);
        w2t_kernel<<<tgrid, 256>>>(w2, pw2b);
    }

    // k = relu(x @ w1^T + b1) -> bf16, single-term
    gemm_bf16_1t_kernel<<<gemm_grid, 256, SMEM_GEMM1>>>(
        pahi, pw1hi, w1_b, pkb, Mrows, Cq, Cq);

    // v = x @ value^T + vb -> tf32-rounded fp32 (3-term)
    gemm_bf16_kernel<1><<<gemm_grid, 256, SMEM_GEMM>>>(
        pahi, palo, pvwhi, pvwlo, value_b, pv, Mrows, Cq, Cq);

    // attention: writes y bf16 hi/lo planes (overwrites x planes)
    dim3 agrid(Tq / BMq, Hq, Bq);              // (32, 16, 2)
    attn2_kernel<<<agrid, 256, SMEM_ATTN>>>(pkb, pv, pw2b, b2, pahi, palo);

    // out = y @ proj^T + pb (fp32 output, 3-term)
    gemm_bf16_kernel<0><<<gemm_grid, 256, SMEM_GEMM>>>(
        pahi, palo, ppwhi, ppwlo, proj_b, out, Mrows, Cq, Cq);
}